// round 3
// baseline (speedup 1.0000x reference)
#include <cuda_runtime.h>
#include <math.h>

#define SEQ    1024
#define DMODEL 1024
#define NQK    32
#define DQK    32
#define NOV    2048
#define BATCH  2
#define VKV    16
#define KVLEN  (SEQ + VKV)   /* 1040 */
#define RATIO  (NOV / NQK)   /* 64 */

// ---------------- scratch (static device globals; no allocation) ----------------
__device__ float g_q   [(size_t)BATCH * NQK * SEQ   * DQK];   // [b][h][s][d]   8 MB
__device__ float g_kext[(size_t)BATCH * NQK * KVLEN * DQK];   // [b][h][j][d]   8.5 MB
__device__ float g_vext[(size_t)BATCH * KVLEN * NOV];         // [b][j][n]     17 MB
__device__ float g_z   [(size_t)BATCH * SEQ * NOV];           // [bs][n]       16.8 MB
__device__ float g_sin [SEQ * 16];
__device__ float g_cos [SEQ * 16];

// ---------------- rotary table: sin/cos[pos][j], freq = 10000^(j/16) ----------------
__global__ void rot_init_kernel() {
    int i = blockIdx.x * blockDim.x + threadIdx.x;
    if (i >= SEQ * 16) return;
    int pos = i >> 4, jm = i & 15;
    float freq = powf(10000.0f, (float)jm * (1.0f / 16.0f));
    float ang = (float)pos / freq;
    g_sin[i] = sinf(ang);
    g_cos[i] = cosf(ang);
}

// ---------------- Q/K projection + bias + rotary ----------------
// grid (32 s-tiles, 32 heads, 2 batch), block 256.
// C tile: 32 rows (s) x 32 cols (d) for BOTH q and k, sharing the A tile.
__global__ void __launch_bounds__(256) proj_qk_kernel(
    const float* __restrict__ resid, const float* __restrict__ Wq,
    const float* __restrict__ Wk, const float* __restrict__ bq,
    const float* __restrict__ bk)
{
    int st = blockIdx.x, h = blockIdx.y, b = blockIdx.z;
    int s0 = st * 32;
    __shared__ float As[32][65];     // padded: conflict-free column reads
    __shared__ float Bq[64][32];
    __shared__ float Bk[64][32];
    __shared__ float Qs[32][33];
    __shared__ float Ks2[32][33];

    int t = threadIdx.x;
    int r = t & 31;          // row within warp (lane)
    int cg = t >> 5;         // col group (warp id), cols cg*4..cg*4+3

    float aq0 = 0.f, aq1 = 0.f, aq2 = 0.f, aq3 = 0.f;
    float ak0 = 0.f, ak1 = 0.f, ak2 = 0.f, ak3 = 0.f;

    const float* A   = resid + ((size_t)b * SEQ + s0) * DMODEL;
    const float* WqH = Wq + (size_t)h * DMODEL * DQK;
    const float* WkH = Wk + (size_t)h * DMODEL * DQK;

    for (int k0 = 0; k0 < DMODEL; k0 += 64) {
        #pragma unroll
        for (int i = 0; i < 8; i++) {
            int idx = t + i * 256;                 // 32x64
            As[idx >> 6][idx & 63] = A[(size_t)(idx >> 6) * DMODEL + k0 + (idx & 63)];
        }
        #pragma unroll
        for (int i = 0; i < 8; i++) {
            int idx = t + i * 256;                 // 64x32
            int kk = idx >> 5, d = idx & 31;
            Bq[kk][d] = WqH[(size_t)(k0 + kk) * DQK + d];
            Bk[kk][d] = WkH[(size_t)(k0 + kk) * DQK + d];
        }
        __syncthreads();
        #pragma unroll
        for (int kk = 0; kk < 64; kk++) {
            float a = As[r][kk];
            float4 q4 = *(const float4*)&Bq[kk][cg * 4];
            float4 k4 = *(const float4*)&Bk[kk][cg * 4];
            aq0 += a * q4.x; aq1 += a * q4.y; aq2 += a * q4.z; aq3 += a * q4.w;
            ak0 += a * k4.x; ak1 += a * k4.y; ak2 += a * k4.z; ak3 += a * k4.w;
        }
        __syncthreads();
    }

    int c0 = cg * 4;
    Qs[r][c0 + 0] = aq0 + bq[h * DQK + c0 + 0];
    Qs[r][c0 + 1] = aq1 + bq[h * DQK + c0 + 1];
    Qs[r][c0 + 2] = aq2 + bq[h * DQK + c0 + 2];
    Qs[r][c0 + 3] = aq3 + bq[h * DQK + c0 + 3];
    Ks2[r][c0 + 0] = ak0 + bk[h * DQK + c0 + 0];
    Ks2[r][c0 + 1] = ak1 + bk[h * DQK + c0 + 1];
    Ks2[r][c0 + 2] = ak2 + bk[h * DQK + c0 + 2];
    Ks2[r][c0 + 3] = ak3 + bk[h * DQK + c0 + 3];
    __syncthreads();

    int pos = s0 + r;
    #pragma unroll
    for (int j = 0; j < 4; j++) {
        int c = c0 + j;
        int jm = c & 15;
        float sn = g_sin[pos * 16 + jm];
        float cs = g_cos[pos * 16 + jm];
        float qv = Qs[r][c], kv = Ks2[r][c];
        float qf = (c < 16) ? -Qs[r][c + 16]  : Qs[r][c - 16];
        float kf = (c < 16) ? -Ks2[r][c + 16] : Ks2[r][c - 16];
        g_q   [(((size_t)b * NQK + h) * SEQ   + pos) * DQK + c] = qv * cs + qf * sn;
        g_kext[(((size_t)b * NQK + h) * KVLEN + pos) * DQK + c] = kv * cs + kf * sn;
    }
}

// ---------------- append virtual k/v (no rotary on virtuals, per reference) ----------------
__global__ void copy_virtual_kernel(const float* __restrict__ vk,
                                    const float* __restrict__ vv)
{
    int i = blockIdx.x * blockDim.x + threadIdx.x;
    if (i < BATCH * NQK * VKV * DQK) {   // 32768: [b][h][t][d]
        int d  = i & 31;
        int tt = (i >> 5) & 15;
        int h  = (i >> 9) & 31;
        int b  = i >> 14;
        g_kext[(((size_t)b * NQK + h) * KVLEN + SEQ + tt) * DQK + d] =
            vk[((size_t)tt * NQK + h) * DQK + d];
    }
    if (i < BATCH * VKV * NOV) {         // 65536: [b][t][n]
        int n  = i & 2047;
        int tt = (i >> 11) & 15;
        int b  = i >> 15;
        g_vext[((size_t)b * KVLEN + SEQ + tt) * NOV + n] = vv[(size_t)tt * NOV + n];
    }
}

// ---------------- V projection: C[bs,n] = resid[bs,:]·W_V[n,:] + b_V[n]  (NT GEMM) ----------------
// grid (32 n-tiles, 32 row-tiles), block 256, 64x64 tile, k-chunk 32, 4x4 per thread.
__global__ void __launch_bounds__(256) proj_v_kernel(
    const float* __restrict__ resid, const float* __restrict__ Wv,
    const float* __restrict__ bv)
{
    int n0 = blockIdx.x * 64, r0 = blockIdx.y * 64;
    __shared__ float As[32][68];
    __shared__ float Bs[32][68];
    int t = threadIdx.x;
    int tr = t >> 4, tc = t & 15;
    float acc[4][4];
    #pragma unroll
    for (int i = 0; i < 4; i++)
        #pragma unroll
        for (int j = 0; j < 4; j++) acc[i][j] = 0.f;

    for (int k0 = 0; k0 < DMODEL; k0 += 32) {
        #pragma unroll
        for (int i = 0; i < 8; i++) {
            int idx = t + i * 256;
            int rr = idx >> 5, kk = idx & 31;
            As[kk][rr] = resid[(size_t)(r0 + rr) * DMODEL + k0 + kk];
            Bs[kk][rr] = Wv  [(size_t)(n0 + rr) * DMODEL + k0 + kk];
        }
        __syncthreads();
        #pragma unroll
        for (int kk = 0; kk < 32; kk++) {
            float4 a4 = *(const float4*)&As[kk][tr * 4];
            float4 b4 = *(const float4*)&Bs[kk][tc * 4];
            float a[4] = {a4.x, a4.y, a4.z, a4.w};
            float bb[4] = {b4.x, b4.y, b4.z, b4.w};
            #pragma unroll
            for (int ri = 0; ri < 4; ri++)
                #pragma unroll
                for (int ci = 0; ci < 4; ci++) acc[ri][ci] += a[ri] * bb[ci];
        }
        __syncthreads();
    }
    #pragma unroll
    for (int ri = 0; ri < 4; ri++) {
        int row = r0 + tr * 4 + ri;                // global bs
        int b = row >> 10, s = row & 1023;
        #pragma unroll
        for (int ci = 0; ci < 4; ci++) {
            int n = n0 + tc * 4 + ci;
            g_vext[((size_t)b * KVLEN + s) * NOV + n] = acc[ri][ci] + bv[n];
        }
    }
}

// ---------------- attention per (b,h): flash-style online softmax ----------------
// grid (16 q-tiles of 64 rows, 32 heads, 2 batch), block 256.
// Thread (r=t>>2, cg=t&3): owns score row r, cols cg*16..cg*16+15; z cols same.
// Mask: kv index j valid iff j <= i+VKV && j < KVLEN. Chunks truncated per tile.
__global__ void __launch_bounds__(256) attn_kernel()
{
    int qt = blockIdx.x, h = blockIdx.y, b = blockIdx.z;
    int i0 = qt * 64;
    int t = threadIdx.x;
    int r = t >> 2, cg = t & 3;

    __shared__ float Ks[64][36];   // [j][d], 144B rows (16B-aligned float4)
    __shared__ float Vs[64][68];   // [j][rv]
    __shared__ float Ps[64][65];   // [r][j]

    const float invscale = 0.17677669529663687f;  // 1/sqrt(32)
    float qreg[32];
    {
        const float* qp = g_q + (((size_t)b * NQK + h) * SEQ + i0 + r) * DQK;
        #pragma unroll
        for (int d = 0; d < 32; d++) qreg[d] = qp[d] * invscale;
    }

    float m = -INFINITY, l = 0.f;
    float z[16];
    #pragma unroll
    for (int i = 0; i < 16; i++) z[i] = 0.f;

    int myrow = i0 + r;
    int jlim = i0 + 64 + VKV;           // max allowed kv for this tile (exclusive)
    if (jlim > KVLEN) jlim = KVLEN;
    int nch = (jlim + 63) >> 6;

    const float* kb = g_kext + ((size_t)b * NQK + h) * KVLEN * DQK;
    const float* vb = g_vext + (size_t)b * KVLEN * NOV + h * RATIO;

    for (int ch = 0; ch < nch; ch++) {
        int kv0 = ch << 6;
        #pragma unroll
        for (int i = 0; i < 8; i++) {
            int idx = t + i * 256;                 // 64x32
            int j = idx >> 5, d = idx & 31;
            int gj = kv0 + j;
            Ks[j][d] = (gj < KVLEN) ? kb[(size_t)gj * DQK + d] : 0.f;
        }
        #pragma unroll
        for (int i = 0; i < 16; i++) {
            int idx = t + i * 256;                 // 64x64
            int j = idx >> 6, c = idx & 63;
            int gj = kv0 + j;
            Vs[j][c] = (gj < KVLEN) ? vb[(size_t)gj * NOV + c] : 0.f;
        }
        __syncthreads();

        float s[16];
        #pragma unroll
        for (int jj = 0; jj < 16; jj++) {
            int j = cg * 16 + jj;
            float acc = 0.f;
            #pragma unroll
            for (int d4 = 0; d4 < 8; d4++) {
                float4 k4 = *(const float4*)&Ks[j][d4 * 4];
                acc += qreg[4 * d4 + 0] * k4.x + qreg[4 * d4 + 1] * k4.y
                     + qreg[4 * d4 + 2] * k4.z + qreg[4 * d4 + 3] * k4.w;
            }
            int gj = kv0 + j;
            bool ok = (gj <= myrow + VKV) && (gj < KVLEN);
            s[jj] = ok ? acc : -INFINITY;
        }

        // row max across the 4 lanes sharing r
        float mloc = s[0];
        #pragma unroll
        for (int jj = 1; jj < 16; jj++) mloc = fmaxf(mloc, s[jj]);
        mloc = fmaxf(mloc, __shfl_xor_sync(0xFFFFFFFFu, mloc, 1));
        mloc = fmaxf(mloc, __shfl_xor_sync(0xFFFFFFFFu, mloc, 2));
        float mnew = fmaxf(m, mloc);
        float corr = __expf(m - mnew);   // m=-inf only before first (always-valid) chunk

        float psum = 0.f;
        #pragma unroll
        for (int jj = 0; jj < 16; jj++) {
            float p = __expf(s[jj] - mnew);   // exp(-inf) = 0 handles mask
            s[jj] = p;
            psum += p;
        }
        psum += __shfl_xor_sync(0xFFFFFFFFu, psum, 1);
        psum += __shfl_xor_sync(0xFFFFFFFFu, psum, 2);
        l = l * corr + psum;
        m = mnew;
        #pragma unroll
        for (int i = 0; i < 16; i++) z[i] *= corr;
        #pragma unroll
        for (int jj = 0; jj < 16; jj++) Ps[r][cg * 16 + jj] = s[jj];
        __syncthreads();

        #pragma unroll
        for (int j = 0; j < 64; j++) {
            float p = Ps[r][j];
            #pragma unroll
            for (int i4 = 0; i4 < 4; i4++) {
                float4 v4 = *(const float4*)&Vs[j][cg * 16 + i4 * 4];
                z[i4 * 4 + 0] += p * v4.x;
                z[i4 * 4 + 1] += p * v4.y;
                z[i4 * 4 + 2] += p * v4.z;
                z[i4 * 4 + 3] += p * v4.w;
            }
        }
        __syncthreads();
    }

    float linv = 1.f / l;
    float* zp = g_z + ((size_t)b * SEQ + i0 + r) * NOV + h * RATIO + cg * 16;
    #pragma unroll
    for (int i = 0; i < 16; i++) zp[i] = z[i] * linv;
}

// ---------------- output: out[bs,m] = z[bs,:] @ W_O[:,m]  (TN GEMM) ----------------
// grid (16 n-tiles, 32 row-tiles), block 256, 64x64 tile, k-chunk 32.
__global__ void __launch_bounds__(256) out_gemm_kernel(
    const float* __restrict__ Wo, float* __restrict__ out)
{
    int n0 = blockIdx.x * 64, r0 = blockIdx.y * 64;
    __shared__ float As[32][68];
    __shared__ float Bs[32][68];
    int t = threadIdx.x;
    int tr = t >> 4, tc = t & 15;
    float acc[4][4];
    #pragma unroll
    for (int i = 0; i < 4; i++)
        #pragma unroll
        for (int j = 0; j < 4; j++) acc[i][j] = 0.f;

    for (int k0 = 0; k0 < NOV; k0 += 32) {
        #pragma unroll
        for (int i = 0; i < 8; i++) {
            int idx = t + i * 256;
            int rr = idx >> 5, kk = idx & 31;
            As[kk][rr] = g_z[(size_t)(r0 + rr) * NOV + k0 + kk];
        }
        #pragma unroll
        for (int i = 0; i < 8; i++) {
            int idx = t + i * 256;
            int kk = idx >> 6, cc = idx & 63;
            Bs[kk][cc] = Wo[(size_t)(k0 + kk) * DMODEL + n0 + cc];
        }
        __syncthreads();
        #pragma unroll
        for (int kk = 0; kk < 32; kk++) {
            float4 a4 = *(const float4*)&As[kk][tr * 4];
            float4 b4 = *(const float4*)&Bs[kk][tc * 4];
            float a[4] = {a4.x, a4.y, a4.z, a4.w};
            float bb[4] = {b4.x, b4.y, b4.z, b4.w};
            #pragma unroll
            for (int ri = 0; ri < 4; ri++)
                #pragma unroll
                for (int ci = 0; ci < 4; ci++) acc[ri][ci] += a[ri] * bb[ci];
        }
        __syncthreads();
    }
    #pragma unroll
    for (int ri = 0; ri < 4; ri++) {
        int row = r0 + tr * 4 + ri;
        #pragma unroll
        for (int ci = 0; ci < 4; ci++)
            out[(size_t)row * DMODEL + n0 + tc * 4 + ci] = acc[ri][ci];
    }
}

// ---------------- launch ----------------
extern "C" void kernel_launch(void* const* d_in, const int* in_sizes, int n_in,
                              void* d_out, int out_size)
{
    const float* resid = (const float*)d_in[0];
    const float* Wq    = (const float*)d_in[1];
    const float* Wk    = (const float*)d_in[2];
    const float* Wv    = (const float*)d_in[3];
    const float* Wo    = (const float*)d_in[4];
    const float* bq    = (const float*)d_in[5];
    const float* bk    = (const float*)d_in[6];
    const float* bv    = (const float*)d_in[7];
    const float* vk    = (const float*)d_in[8];
    const float* vv    = (const float*)d_in[9];
    float* out = (float*)d_out;

    rot_init_kernel<<<64, 256>>>();
    copy_virtual_kernel<<<256, 256>>>(vk, vv);
    proj_qk_kernel<<<dim3(32, 32, 2), 256>>>(resid, Wq, Wk, bq, bk);
    proj_v_kernel<<<dim3(32, 32), 256>>>(resid, Wv, bv);
    attn_kernel<<<dim3(16, 32, 2), 256>>>();
    out_gemm_kernel<<<dim3(16, 32), 256>>>(Wo, out);
}

// round 4
// speedup vs baseline: 1.4222x; 1.4222x over previous
#include <cuda_runtime.h>
#include <math.h>
#include <stdint.h>

#define SEQ    1024
#define DMODEL 1024
#define NQK    32
#define DQK    32
#define NOV    2048
#define BATCH  2
#define VKV    16
#define KVLEN  (SEQ + VKV)   /* 1040 */
#define RATIO  (NOV / NQK)   /* 64 */

// ---------------- scratch (static device globals; no allocation) ----------------
__device__ float g_q   [(size_t)BATCH * NQK * SEQ   * DQK];   // [b][h][s][d]
__device__ float g_kext[(size_t)BATCH * NQK * KVLEN * DQK];   // [b][h][j][d]
__device__ float g_vext[(size_t)BATCH * KVLEN * NOV];         // [b][j][n]
__device__ float g_z   [(size_t)BATCH * SEQ * NOV];           // [bs][n]
__device__ float g_sin [SEQ * 16];
__device__ float g_cos [SEQ * 16];

// ---------------- tf32 mma helpers ----------------
__device__ __forceinline__ uint32_t f2tf(float x) {
    uint32_t y;
    asm("cvt.rna.tf32.f32 %0, %1;" : "=r"(y) : "f"(x));
    return y;
}

// D += A(16x8,row) * B(8x8,col), tf32 in, f32 accum.
__device__ __forceinline__ void mma8(float4& d, const uint32_t* a, const uint32_t* b) {
    asm volatile(
        "mma.sync.aligned.m16n8k8.row.col.f32.tf32.tf32.f32 "
        "{%0,%1,%2,%3}, {%4,%5,%6,%7}, {%8,%9}, {%0,%1,%2,%3};\n"
        : "+f"(d.x), "+f"(d.y), "+f"(d.z), "+f"(d.w)
        : "r"(a[0]), "r"(a[1]), "r"(a[2]), "r"(a[3]), "r"(b[0]), "r"(b[1]));
}

// ---------------- rotary table ----------------
__global__ void rot_init_kernel() {
    int i = blockIdx.x * blockDim.x + threadIdx.x;
    if (i >= SEQ * 16) return;
    int pos = i >> 4, jm = i & 15;
    float freq = powf(10000.0f, (float)jm * (1.0f / 16.0f));
    float ang = (float)pos / freq;
    g_sin[i] = sinf(ang);
    g_cos[i] = cosf(ang);
}

// ---------------- append virtual k/v ----------------
__global__ void copy_virtual_kernel(const float* __restrict__ vk,
                                    const float* __restrict__ vv)
{
    int i = blockIdx.x * blockDim.x + threadIdx.x;
    if (i < BATCH * NQK * VKV * DQK) {
        int d  = i & 31;
        int tt = (i >> 5) & 15;
        int h  = (i >> 9) & 31;
        int b  = i >> 14;
        g_kext[(((size_t)b * NQK + h) * KVLEN + SEQ + tt) * DQK + d] =
            vk[((size_t)tt * NQK + h) * DQK + d];
    }
    if (i < BATCH * VKV * NOV) {
        int n  = i & 2047;
        int tt = (i >> 11) & 15;
        int b  = i >> 15;
        g_vext[((size_t)b * KVLEN + SEQ + tt) * NOV + n] = vv[(size_t)tt * NOV + n];
    }
}

// ---------------- Q/K projection (tf32 mma) + bias + rotary ----------------
// grid (16 m-tiles of 128 rows, 32 heads), block 256 (8 warps, 4Mx2N).
// BM=128, BN=64 (cols 0..31 = q dims, 32..63 = k dims), BK=32.
__global__ void __launch_bounds__(256) proj_qk_kernel(
    const float* __restrict__ resid, const float* __restrict__ Wq,
    const float* __restrict__ Wk, const float* __restrict__ bq,
    const float* __restrict__ bk)
{
    __shared__ __align__(16) char sraw[34816];
    uint32_t (*As)[36]  = (uint32_t(*)[36])sraw;                 // 128x36 = 18432B
    uint32_t (*Bs2)[68] = (uint32_t(*)[68])(sraw + 18432);       // 32x68  =  8704B
    float    (*Cs)[68]  = (float(*)[68])sraw;                    // 128x68 = 34816B (aliases)

    int r0 = blockIdx.x * 128;
    int h  = blockIdx.y;
    int t = threadIdx.x;
    int w = t >> 5, lane = t & 31;
    int g = lane >> 2, tg = lane & 3;
    int wm = w >> 1, wn = w & 1;

    float4 acc[2][4];
    #pragma unroll
    for (int i = 0; i < 2; i++)
        #pragma unroll
        for (int j = 0; j < 4; j++) acc[i][j] = make_float4(0.f, 0.f, 0.f, 0.f);

    const float* WqH = Wq + (size_t)h * DMODEL * DQK;
    const float* WkH = Wk + (size_t)h * DMODEL * DQK;

    for (int k0 = 0; k0 < DMODEL; k0 += 32) {
        #pragma unroll
        for (int i = 0; i < 4; i++) {                 // A: 128x32
            int idx = t + i * 256;
            int row = idx >> 3, kq = (idx & 7) << 2;
            float4 a = *(const float4*)(resid + (size_t)(r0 + row) * DMODEL + k0 + kq);
            uint4 ua = make_uint4(f2tf(a.x), f2tf(a.y), f2tf(a.z), f2tf(a.w));
            *(uint4*)&As[row][kq] = ua;
        }
        #pragma unroll
        for (int i = 0; i < 2; i++) {                 // B: 32(k) x 64(n)
            int idx = t + i * 256;
            int kk = idx >> 4, nq = idx & 15;
            int n = nq << 2;
            const float* src = (n < 32)
                ? WqH + (size_t)(k0 + kk) * DQK + n
                : WkH + (size_t)(k0 + kk) * DQK + (n - 32);
            float4 bvv = *(const float4*)src;
            uint4 ub = make_uint4(f2tf(bvv.x), f2tf(bvv.y), f2tf(bvv.z), f2tf(bvv.w));
            *(uint4*)&Bs2[kk][n] = ub;
        }
        __syncthreads();
        #pragma unroll
        for (int ks = 0; ks < 32; ks += 8) {
            uint32_t af[2][4];
            #pragma unroll
            for (int i = 0; i < 2; i++) {
                int rm = wm * 32 + i * 16;
                af[i][0] = As[rm + g    ][ks + tg];
                af[i][1] = As[rm + g + 8][ks + tg];
                af[i][2] = As[rm + g    ][ks + tg + 4];
                af[i][3] = As[rm + g + 8][ks + tg + 4];
            }
            #pragma unroll
            for (int j = 0; j < 4; j++) {
                int cn = wn * 32 + j * 8 + g;
                uint32_t bf[2] = { Bs2[ks + tg][cn], Bs2[ks + tg + 4][cn] };
                mma8(acc[0][j], af[0], bf);
                mma8(acc[1][j], af[1], bf);
            }
        }
        __syncthreads();
    }

    // write accum + bias into Cs
    #pragma unroll
    for (int i = 0; i < 2; i++) {
        int rr = wm * 32 + i * 16 + g;
        #pragma unroll
        for (int j = 0; j < 4; j++) {
            int c = wn * 32 + j * 8 + tg * 2;
            float b0 = (c < 32)     ? bq[h * DQK + c]          : bk[h * DQK + c - 32];
            float b1 = (c + 1 < 32) ? bq[h * DQK + c + 1]      : bk[h * DQK + c + 1 - 32];
            Cs[rr    ][c    ] = acc[i][j].x + b0;
            Cs[rr    ][c + 1] = acc[i][j].y + b1;
            Cs[rr + 8][c    ] = acc[i][j].z + b0;
            Cs[rr + 8][c + 1] = acc[i][j].w + b1;
        }
    }
    __syncthreads();

    // rotary + scatter: thread handles (row = t>>1, half = t&1)
    {
        int r = t >> 1, half = t & 1;
        int grow = r0 + r;
        int bb = grow >> 10, pos = grow & 1023;
        const float* base = &Cs[r][half * 32];
        float* dst = half == 0
            ? g_q    + (((size_t)bb * NQK + h) * SEQ   + pos) * DQK
            : g_kext + (((size_t)bb * NQK + h) * KVLEN + pos) * DQK;
        #pragma unroll
        for (int c = 0; c < 32; c++) {
            float val  = base[c];
            float flip = (c < 16) ? -base[c + 16] : base[c - 16];
            int jm = c & 15;
            float sn = g_sin[pos * 16 + jm];
            float cs = g_cos[pos * 16 + jm];
            dst[c] = val * cs + flip * sn;
        }
    }
}

// ---------------- V projection (tf32 mma, NT): C[bs,n] = resid @ Wv^T + bv ----------------
// grid (16 n-tiles, 16 m-tiles), block 256, BM=BN=128, BK=32, warp tile 32x64.
__global__ void __launch_bounds__(256) proj_v_kernel(
    const float* __restrict__ resid, const float* __restrict__ Wv,
    const float* __restrict__ bv)
{
    __shared__ uint32_t As[128][36];
    __shared__ uint32_t Bs[128][36];
    int n0 = blockIdx.x * 128, r0 = blockIdx.y * 128;
    int t = threadIdx.x;
    int w = t >> 5, lane = t & 31;
    int g = lane >> 2, tg = lane & 3;
    int wm = w >> 1, wn = w & 1;

    float4 acc[2][8];
    #pragma unroll
    for (int i = 0; i < 2; i++)
        #pragma unroll
        for (int j = 0; j < 8; j++) acc[i][j] = make_float4(0.f, 0.f, 0.f, 0.f);

    for (int k0 = 0; k0 < DMODEL; k0 += 32) {
        #pragma unroll
        for (int i = 0; i < 4; i++) {
            int idx = t + i * 256;
            int row = idx >> 3, kq = (idx & 7) << 2;
            float4 a = *(const float4*)(resid + (size_t)(r0 + row) * DMODEL + k0 + kq);
            *(uint4*)&As[row][kq] = make_uint4(f2tf(a.x), f2tf(a.y), f2tf(a.z), f2tf(a.w));
            float4 b = *(const float4*)(Wv + (size_t)(n0 + row) * DMODEL + k0 + kq);
            *(uint4*)&Bs[row][kq] = make_uint4(f2tf(b.x), f2tf(b.y), f2tf(b.z), f2tf(b.w));
        }
        __syncthreads();
        #pragma unroll
        for (int ks = 0; ks < 32; ks += 8) {
            uint32_t af[2][4];
            #pragma unroll
            for (int i = 0; i < 2; i++) {
                int rm = wm * 32 + i * 16;
                af[i][0] = As[rm + g    ][ks + tg];
                af[i][1] = As[rm + g + 8][ks + tg];
                af[i][2] = As[rm + g    ][ks + tg + 4];
                af[i][3] = As[rm + g + 8][ks + tg + 4];
            }
            #pragma unroll
            for (int j = 0; j < 8; j++) {
                int cn = wn * 64 + j * 8 + g;
                uint32_t bf[2] = { Bs[cn][ks + tg], Bs[cn][ks + tg + 4] };
                mma8(acc[0][j], af[0], bf);
                mma8(acc[1][j], af[1], bf);
            }
        }
        __syncthreads();
    }

    #pragma unroll
    for (int i = 0; i < 2; i++) {
        int row0 = r0 + wm * 32 + i * 16 + g;
        #pragma unroll
        for (int j = 0; j < 8; j++) {
            int n = n0 + wn * 64 + j * 8 + tg * 2;
            float2 bvv = *(const float2*)(bv + n);
            int b1 = row0 >> 10, s1 = row0 & 1023;
            float2 o1 = make_float2(acc[i][j].x + bvv.x, acc[i][j].y + bvv.y);
            *(float2*)&g_vext[((size_t)b1 * KVLEN + s1) * NOV + n] = o1;
            int r2 = row0 + 8;
            int b2 = r2 >> 10, s2 = r2 & 1023;
            float2 o2 = make_float2(acc[i][j].z + bvv.x, acc[i][j].w + bvv.y);
            *(float2*)&g_vext[((size_t)b2 * KVLEN + s2) * NOV + n] = o2;
        }
    }
}

// ---------------- attention per (b,h): flash-style online softmax (unchanged) ----------------
__global__ void __launch_bounds__(256) attn_kernel()
{
    int qt = blockIdx.x, h = blockIdx.y, b = blockIdx.z;
    int i0 = qt * 64;
    int t = threadIdx.x;
    int r = t >> 2, cg = t & 3;

    __shared__ float Ks[64][36];
    __shared__ float Vs[64][68];
    __shared__ float Ps[64][65];

    const float invscale = 0.17677669529663687f;  // 1/sqrt(32)
    float qreg[32];
    {
        const float* qp = g_q + (((size_t)b * NQK + h) * SEQ + i0 + r) * DQK;
        #pragma unroll
        for (int d = 0; d < 32; d++) qreg[d] = qp[d] * invscale;
    }

    float m = -INFINITY, l = 0.f;
    float z[16];
    #pragma unroll
    for (int i = 0; i < 16; i++) z[i] = 0.f;

    int myrow = i0 + r;
    int jlim = i0 + 64 + VKV;
    if (jlim > KVLEN) jlim = KVLEN;
    int nch = (jlim + 63) >> 6;

    const float* kb = g_kext + ((size_t)b * NQK + h) * KVLEN * DQK;
    const float* vb = g_vext + (size_t)b * KVLEN * NOV + h * RATIO;

    for (int ch = 0; ch < nch; ch++) {
        int kv0 = ch << 6;
        #pragma unroll
        for (int i = 0; i < 8; i++) {
            int idx = t + i * 256;
            int j = idx >> 5, d = idx & 31;
            int gj = kv0 + j;
            Ks[j][d] = (gj < KVLEN) ? kb[(size_t)gj * DQK + d] : 0.f;
        }
        #pragma unroll
        for (int i = 0; i < 16; i++) {
            int idx = t + i * 256;
            int j = idx >> 6, c = idx & 63;
            int gj = kv0 + j;
            Vs[j][c] = (gj < KVLEN) ? vb[(size_t)gj * NOV + c] : 0.f;
        }
        __syncthreads();

        float s[16];
        #pragma unroll
        for (int jj = 0; jj < 16; jj++) {
            int j = cg * 16 + jj;
            float acc = 0.f;
            #pragma unroll
            for (int d4 = 0; d4 < 8; d4++) {
                float4 k4 = *(const float4*)&Ks[j][d4 * 4];
                acc += qreg[4 * d4 + 0] * k4.x + qreg[4 * d4 + 1] * k4.y
                     + qreg[4 * d4 + 2] * k4.z + qreg[4 * d4 + 3] * k4.w;
            }
            int gj = kv0 + j;
            bool ok = (gj <= myrow + VKV) && (gj < KVLEN);
            s[jj] = ok ? acc : -INFINITY;
        }

        float mloc = s[0];
        #pragma unroll
        for (int jj = 1; jj < 16; jj++) mloc = fmaxf(mloc, s[jj]);
        mloc = fmaxf(mloc, __shfl_xor_sync(0xFFFFFFFFu, mloc, 1));
        mloc = fmaxf(mloc, __shfl_xor_sync(0xFFFFFFFFu, mloc, 2));
        float mnew = fmaxf(m, mloc);
        float corr = __expf(m - mnew);

        float psum = 0.f;
        #pragma unroll
        for (int jj = 0; jj < 16; jj++) {
            float p = __expf(s[jj] - mnew);
            s[jj] = p;
            psum += p;
        }
        psum += __shfl_xor_sync(0xFFFFFFFFu, psum, 1);
        psum += __shfl_xor_sync(0xFFFFFFFFu, psum, 2);
        l = l * corr + psum;
        m = mnew;
        #pragma unroll
        for (int i = 0; i < 16; i++) z[i] *= corr;
        #pragma unroll
        for (int jj = 0; jj < 16; jj++) Ps[r][cg * 16 + jj] = s[jj];
        __syncthreads();

        #pragma unroll
        for (int j = 0; j < 64; j++) {
            float p = Ps[r][j];
            #pragma unroll
            for (int i4 = 0; i4 < 4; i4++) {
                float4 v4 = *(const float4*)&Vs[j][cg * 16 + i4 * 4];
                z[i4 * 4 + 0] += p * v4.x;
                z[i4 * 4 + 1] += p * v4.y;
                z[i4 * 4 + 2] += p * v4.z;
                z[i4 * 4 + 3] += p * v4.w;
            }
        }
        __syncthreads();
    }

    float linv = 1.f / l;
    float* zp = g_z + ((size_t)b * SEQ + i0 + r) * NOV + h * RATIO + cg * 16;
    #pragma unroll
    for (int i = 0; i < 16; i++) zp[i] = z[i] * linv;
}

// ---------------- output (tf32 mma, NN): out[bs,m] = z @ Wo ----------------
// grid (8 n-tiles, 16 m-tiles), block 256, BM=BN=128, BK=32, K=2048.
__global__ void __launch_bounds__(256) out_gemm_kernel(
    const float* __restrict__ Wo, float* __restrict__ out)
{
    __shared__ uint32_t As[128][36];
    __shared__ uint32_t Bs2[32][132];
    int n0 = blockIdx.x * 128, r0 = blockIdx.y * 128;
    int t = threadIdx.x;
    int w = t >> 5, lane = t & 31;
    int g = lane >> 2, tg = lane & 3;
    int wm = w >> 1, wn = w & 1;

    float4 acc[2][8];
    #pragma unroll
    for (int i = 0; i < 2; i++)
        #pragma unroll
        for (int j = 0; j < 8; j++) acc[i][j] = make_float4(0.f, 0.f, 0.f, 0.f);

    for (int k0 = 0; k0 < NOV; k0 += 32) {
        #pragma unroll
        for (int i = 0; i < 4; i++) {
            int idx = t + i * 256;
            int row = idx >> 3, kq = (idx & 7) << 2;
            float4 a = *(const float4*)(g_z + (size_t)(r0 + row) * NOV + k0 + kq);
            *(uint4*)&As[row][kq] = make_uint4(f2tf(a.x), f2tf(a.y), f2tf(a.z), f2tf(a.w));
        }
        #pragma unroll
        for (int i = 0; i < 4; i++) {                 // B: 32(k) x 128(n)
            int idx = t + i * 256;
            int kk = idx >> 5, nq = idx & 31;
            int n = nq << 2;
            float4 b = *(const float4*)(Wo + (size_t)(k0 + kk) * DMODEL + n0 + n);
            *(uint4*)&Bs2[kk][n] = make_uint4(f2tf(b.x), f2tf(b.y), f2tf(b.z), f2tf(b.w));
        }
        __syncthreads();
        #pragma unroll
        for (int ks = 0; ks < 32; ks += 8) {
            uint32_t af[2][4];
            #pragma unroll
            for (int i = 0; i < 2; i++) {
                int rm = wm * 32 + i * 16;
                af[i][0] = As[rm + g    ][ks + tg];
                af[i][1] = As[rm + g + 8][ks + tg];
                af[i][2] = As[rm + g    ][ks + tg + 4];
                af[i][3] = As[rm + g + 8][ks + tg + 4];
            }
            #pragma unroll
            for (int j = 0; j < 8; j++) {
                int cn = wn * 64 + j * 8 + g;
                uint32_t bf[2] = { Bs2[ks + tg][cn], Bs2[ks + tg + 4][cn] };
                mma8(acc[0][j], af[0], bf);
                mma8(acc[1][j], af[1], bf);
            }
        }
        __syncthreads();
    }

    #pragma unroll
    for (int i = 0; i < 2; i++) {
        int row0 = r0 + wm * 32 + i * 16 + g;
        #pragma unroll
        for (int j = 0; j < 8; j++) {
            int n = n0 + wn * 64 + j * 8 + tg * 2;
            *(float2*)&out[(size_t)row0 * DMODEL + n] =
                make_float2(acc[i][j].x, acc[i][j].y);
            *(float2*)&out[(size_t)(row0 + 8) * DMODEL + n] =
                make_float2(acc[i][j].z, acc[i][j].w);
        }
    }
}

// ---------------- launch ----------------
extern "C" void kernel_launch(void* const* d_in, const int* in_sizes, int n_in,
                              void* d_out, int out_size)
{
    const float* resid = (const float*)d_in[0];
    const float* Wq    = (const float*)d_in[1];
    const float* Wk    = (const float*)d_in[2];
    const float* Wv    = (const float*)d_in[3];
    const float* Wo    = (const float*)d_in[4];
    const float* bq    = (const float*)d_in[5];
    const float* bk    = (const float*)d_in[6];
    const float* bv    = (const float*)d_in[7];
    const float* vk    = (const float*)d_in[8];
    const float* vv    = (const float*)d_in[9];
    float* out = (float*)d_out;

    rot_init_kernel<<<64, 256>>>();
    copy_virtual_kernel<<<256, 256>>>(vk, vv);
    proj_qk_kernel<<<dim3(16, 32), 256>>>(resid, Wq, Wk, bq, bk);
    proj_v_kernel<<<dim3(16, 16), 256>>>(resid, Wv, bv);
    attn_kernel<<<dim3(16, 32, 2), 256>>>();
    out_gemm_kernel<<<dim3(8, 16), 256>>>(Wo, out);
}

// round 5
// speedup vs baseline: 5.4265x; 3.8156x over previous
#include <cuda_runtime.h>
#include <math.h>
#include <stdint.h>

#define SEQ    1024
#define DMODEL 1024
#define NQK    32
#define DQK    32
#define NOV    2048
#define BATCH  2
#define VKV    16
#define KVLEN  (SEQ + VKV)   /* 1040 */
#define RATIO  (NOV / NQK)   /* 64 */

// ---------------- scratch (static device globals; no allocation) ----------------
__device__ float g_q   [(size_t)BATCH * NQK * SEQ   * DQK];   // [b][h][s][d]  (pre-scaled by 1/sqrt(32))
__device__ float g_kext[(size_t)BATCH * NQK * KVLEN * DQK];   // [b][h][j][d]
__device__ float g_vext[(size_t)BATCH * KVLEN * NOV];         // [b][j][n]
__device__ float g_z   [(size_t)BATCH * SEQ * NOV];           // [bs][n]
__device__ float g_sin [SEQ * 16];
__device__ float g_cos [SEQ * 16];

// ---------------- tf32 mma helpers ----------------
__device__ __forceinline__ uint32_t f2tf(float x) {
    uint32_t y;
    asm("cvt.rna.tf32.f32 %0, %1;" : "=r"(y) : "f"(x));
    return y;
}

__device__ __forceinline__ void mma8(float4& d, const uint32_t* a, const uint32_t* b) {
    asm volatile(
        "mma.sync.aligned.m16n8k8.row.col.f32.tf32.tf32.f32 "
        "{%0,%1,%2,%3}, {%4,%5,%6,%7}, {%8,%9}, {%0,%1,%2,%3};\n"
        : "+f"(d.x), "+f"(d.y), "+f"(d.z), "+f"(d.w)
        : "r"(a[0]), "r"(a[1]), "r"(a[2]), "r"(a[3]), "r"(b[0]), "r"(b[1]));
}

// ---------------- rotary table ----------------
__global__ void rot_init_kernel() {
    int i = blockIdx.x * blockDim.x + threadIdx.x;
    if (i >= SEQ * 16) return;
    int pos = i >> 4, jm = i & 15;
    float freq = powf(10000.0f, (float)jm * (1.0f / 16.0f));
    float ang = (float)pos / freq;
    g_sin[i] = sinf(ang);
    g_cos[i] = cosf(ang);
}

// ---------------- append virtual k/v ----------------
__global__ void copy_virtual_kernel(const float* __restrict__ vk,
                                    const float* __restrict__ vv)
{
    int i = blockIdx.x * blockDim.x + threadIdx.x;
    if (i < BATCH * NQK * VKV * DQK) {
        int d  = i & 31;
        int tt = (i >> 5) & 15;
        int h  = (i >> 9) & 31;
        int b  = i >> 14;
        g_kext[(((size_t)b * NQK + h) * KVLEN + SEQ + tt) * DQK + d] =
            vk[((size_t)tt * NQK + h) * DQK + d];
    }
    if (i < BATCH * VKV * NOV) {
        int n  = i & 2047;
        int tt = (i >> 11) & 15;
        int b  = i >> 15;
        g_vext[((size_t)b * KVLEN + SEQ + tt) * NOV + n] = vv[(size_t)tt * NOV + n];
    }
}

// ---------------- Q/K projection (tf32 mma) + bias + rotary (+1/sqrt(32) on q) ----------------
__global__ void __launch_bounds__(256) proj_qk_kernel(
    const float* __restrict__ resid, const float* __restrict__ Wq,
    const float* __restrict__ Wk, const float* __restrict__ bq,
    const float* __restrict__ bk)
{
    __shared__ __align__(16) char sraw[34816];
    uint32_t (*As)[36]  = (uint32_t(*)[36])sraw;
    uint32_t (*Bs2)[68] = (uint32_t(*)[68])(sraw + 18432);
    float    (*Cs)[68]  = (float(*)[68])sraw;      // aliases (after last use of As/Bs2)

    int r0 = blockIdx.x * 128;
    int h  = blockIdx.y;
    int t = threadIdx.x;
    int w = t >> 5, lane = t & 31;
    int g = lane >> 2, tg = lane & 3;
    int wm = w >> 1, wn = w & 1;

    float4 acc[2][4];
    #pragma unroll
    for (int i = 0; i < 2; i++)
        #pragma unroll
        for (int j = 0; j < 4; j++) acc[i][j] = make_float4(0.f, 0.f, 0.f, 0.f);

    const float* WqH = Wq + (size_t)h * DMODEL * DQK;
    const float* WkH = Wk + (size_t)h * DMODEL * DQK;

    for (int k0 = 0; k0 < DMODEL; k0 += 32) {
        #pragma unroll
        for (int i = 0; i < 4; i++) {
            int idx = t + i * 256;
            int row = idx >> 3, kq = (idx & 7) << 2;
            float4 a = *(const float4*)(resid + (size_t)(r0 + row) * DMODEL + k0 + kq);
            *(uint4*)&As[row][kq] = make_uint4(f2tf(a.x), f2tf(a.y), f2tf(a.z), f2tf(a.w));
        }
        #pragma unroll
        for (int i = 0; i < 2; i++) {
            int idx = t + i * 256;
            int kk = idx >> 4, nq = idx & 15;
            int n = nq << 2;
            const float* src = (n < 32)
                ? WqH + (size_t)(k0 + kk) * DQK + n
                : WkH + (size_t)(k0 + kk) * DQK + (n - 32);
            float4 bvv = *(const float4*)src;
            *(uint4*)&Bs2[kk][n] = make_uint4(f2tf(bvv.x), f2tf(bvv.y), f2tf(bvv.z), f2tf(bvv.w));
        }
        __syncthreads();
        #pragma unroll
        for (int ks = 0; ks < 32; ks += 8) {
            uint32_t af[2][4];
            #pragma unroll
            for (int i = 0; i < 2; i++) {
                int rm = wm * 32 + i * 16;
                af[i][0] = As[rm + g    ][ks + tg];
                af[i][1] = As[rm + g + 8][ks + tg];
                af[i][2] = As[rm + g    ][ks + tg + 4];
                af[i][3] = As[rm + g + 8][ks + tg + 4];
            }
            #pragma unroll
            for (int j = 0; j < 4; j++) {
                int cn = wn * 32 + j * 8 + g;
                uint32_t bf[2] = { Bs2[ks + tg][cn], Bs2[ks + tg + 4][cn] };
                mma8(acc[0][j], af[0], bf);
                mma8(acc[1][j], af[1], bf);
            }
        }
        __syncthreads();
    }

    #pragma unroll
    for (int i = 0; i < 2; i++) {
        int rr = wm * 32 + i * 16 + g;
        #pragma unroll
        for (int j = 0; j < 4; j++) {
            int c = wn * 32 + j * 8 + tg * 2;
            float b0 = (c < 32)     ? bq[h * DQK + c]     : bk[h * DQK + c - 32];
            float b1 = (c + 1 < 32) ? bq[h * DQK + c + 1] : bk[h * DQK + c + 1 - 32];
            Cs[rr    ][c    ] = acc[i][j].x + b0;
            Cs[rr    ][c + 1] = acc[i][j].y + b1;
            Cs[rr + 8][c    ] = acc[i][j].z + b0;
            Cs[rr + 8][c + 1] = acc[i][j].w + b1;
        }
    }
    __syncthreads();

    {
        int r = t >> 1, half = t & 1;
        int grow = r0 + r;
        int bb = grow >> 10, pos = grow & 1023;
        const float invscale = 0.17677669529663687f;   // 1/sqrt(32)
        float sc = (half == 0) ? invscale : 1.f;
        const float* base = &Cs[r][half * 32];
        float* dst = half == 0
            ? g_q    + (((size_t)bb * NQK + h) * SEQ   + pos) * DQK
            : g_kext + (((size_t)bb * NQK + h) * KVLEN + pos) * DQK;
        #pragma unroll
        for (int c = 0; c < 32; c++) {
            float val  = base[c];
            float flip = (c < 16) ? -base[c + 16] : base[c - 16];
            int jm = c & 15;
            float sn = g_sin[pos * 16 + jm];
            float cs = g_cos[pos * 16 + jm];
            dst[c] = (val * cs + flip * sn) * sc;
        }
    }
}

// ---------------- V projection (tf32 mma, NT) ----------------
__global__ void __launch_bounds__(256) proj_v_kernel(
    const float* __restrict__ resid, const float* __restrict__ Wv,
    const float* __restrict__ bv)
{
    __shared__ uint32_t As[128][36];
    __shared__ uint32_t Bs[128][36];
    int n0 = blockIdx.x * 128, r0 = blockIdx.y * 128;
    int t = threadIdx.x;
    int w = t >> 5, lane = t & 31;
    int g = lane >> 2, tg = lane & 3;
    int wm = w >> 1, wn = w & 1;

    float4 acc[2][8];
    #pragma unroll
    for (int i = 0; i < 2; i++)
        #pragma unroll
        for (int j = 0; j < 8; j++) acc[i][j] = make_float4(0.f, 0.f, 0.f, 0.f);

    for (int k0 = 0; k0 < DMODEL; k0 += 32) {
        #pragma unroll
        for (int i = 0; i < 4; i++) {
            int idx = t + i * 256;
            int row = idx >> 3, kq = (idx & 7) << 2;
            float4 a = *(const float4*)(resid + (size_t)(r0 + row) * DMODEL + k0 + kq);
            *(uint4*)&As[row][kq] = make_uint4(f2tf(a.x), f2tf(a.y), f2tf(a.z), f2tf(a.w));
            float4 b = *(const float4*)(Wv + (size_t)(n0 + row) * DMODEL + k0 + kq);
            *(uint4*)&Bs[row][kq] = make_uint4(f2tf(b.x), f2tf(b.y), f2tf(b.z), f2tf(b.w));
        }
        __syncthreads();
        #pragma unroll
        for (int ks = 0; ks < 32; ks += 8) {
            uint32_t af[2][4];
            #pragma unroll
            for (int i = 0; i < 2; i++) {
                int rm = wm * 32 + i * 16;
                af[i][0] = As[rm + g    ][ks + tg];
                af[i][1] = As[rm + g + 8][ks + tg];
                af[i][2] = As[rm + g    ][ks + tg + 4];
                af[i][3] = As[rm + g + 8][ks + tg + 4];
            }
            #pragma unroll
            for (int j = 0; j < 8; j++) {
                int cn = wn * 64 + j * 8 + g;
                uint32_t bf[2] = { Bs[cn][ks + tg], Bs[cn][ks + tg + 4] };
                mma8(acc[0][j], af[0], bf);
                mma8(acc[1][j], af[1], bf);
            }
        }
        __syncthreads();
    }

    #pragma unroll
    for (int i = 0; i < 2; i++) {
        int row0 = r0 + wm * 32 + i * 16 + g;
        #pragma unroll
        for (int j = 0; j < 8; j++) {
            int n = n0 + wn * 64 + j * 8 + tg * 2;
            float2 bvv = *(const float2*)(bv + n);
            int b1 = row0 >> 10, s1 = row0 & 1023;
            *(float2*)&g_vext[((size_t)b1 * KVLEN + s1) * NOV + n] =
                make_float2(acc[i][j].x + bvv.x, acc[i][j].y + bvv.y);
            int r2 = row0 + 8;
            int b2 = r2 >> 10, s2 = r2 & 1023;
            *(float2*)&g_vext[((size_t)b2 * KVLEN + s2) * NOV + n] =
                make_float2(acc[i][j].z + bvv.x, acc[i][j].w + bvv.y);
        }
    }
}

// ---------------- attention: tf32 mma flash (128-row q tile, 64-wide kv chunks) ----------------
// grid (8, 32, 2), block 256 (8 warps x 16 q-rows). Dynamic smem:
//   Ks [64][36] tf32 | Vs [64][72] tf32 | Ps [128][68] tf32   = 62464 B
__global__ void __launch_bounds__(256) attn_mma_kernel()
{
    extern __shared__ uint32_t smem[];
    uint32_t* Ks = smem;                       // pitch 36
    uint32_t* Vs = smem + 64 * 36;             // pitch 72
    uint32_t* Ps = smem + 64 * 36 + 64 * 72;   // pitch 68

    int qt = blockIdx.x, h = blockIdx.y, b = blockIdx.z;
    int i0 = qt * 128;
    int t = threadIdx.x, w = t >> 5, lane = t & 31;
    int g = lane >> 2, tg = lane & 3;

    // Q fragments (q pre-scaled by 1/sqrt(32) in projection)
    uint32_t qf[4][4];
    {
        const float* qbase = g_q + (((size_t)b * NQK + h) * SEQ + i0 + w * 16) * DQK;
        #pragma unroll
        for (int kb = 0; kb < 4; kb++) {
            qf[kb][0] = f2tf(qbase[(size_t)g       * DQK + kb * 8 + tg]);
            qf[kb][1] = f2tf(qbase[(size_t)(g + 8) * DQK + kb * 8 + tg]);
            qf[kb][2] = f2tf(qbase[(size_t)g       * DQK + kb * 8 + tg + 4]);
            qf[kb][3] = f2tf(qbase[(size_t)(g + 8) * DQK + kb * 8 + tg + 4]);
        }
    }

    float m_lo = -INFINITY, m_hi = -INFINITY, l_lo = 0.f, l_hi = 0.f;
    float4 z[8];
    #pragma unroll
    for (int j = 0; j < 8; j++) z[j] = make_float4(0.f, 0.f, 0.f, 0.f);

    int row_lo = i0 + w * 16 + g;
    int row_hi = row_lo + 8;

    int jlim = i0 + 128 + VKV;
    if (jlim > KVLEN) jlim = KVLEN;
    int nch = (jlim + 63) >> 6;

    const float* kbp = g_kext + ((size_t)b * NQK + h) * KVLEN * DQK;
    const float* vbp = g_vext + (size_t)b * KVLEN * NOV + h * RATIO;

    for (int ch = 0; ch < nch; ch++) {
        int kv0 = ch << 6;
        __syncthreads();
        // K chunk: 64x32
        #pragma unroll
        for (int i = 0; i < 2; i++) {
            int idx = t + i * 256;
            int row = idx >> 3, c4 = (idx & 7) << 2;
            int gj = kv0 + row;
            float4 kx = (gj < KVLEN) ? *(const float4*)(kbp + (size_t)gj * DQK + c4)
                                     : make_float4(0.f, 0.f, 0.f, 0.f);
            *(uint4*)&Ks[row * 36 + c4] = make_uint4(f2tf(kx.x), f2tf(kx.y), f2tf(kx.z), f2tf(kx.w));
        }
        // V chunk: 64x64
        #pragma unroll
        for (int i = 0; i < 4; i++) {
            int idx = t + i * 256;
            int row = idx >> 4, c4 = (idx & 15) << 2;
            int gj = kv0 + row;
            float4 vx = (gj < KVLEN) ? *(const float4*)(vbp + (size_t)gj * NOV + c4)
                                     : make_float4(0.f, 0.f, 0.f, 0.f);
            *(uint4*)&Vs[row * 72 + c4] = make_uint4(f2tf(vx.x), f2tf(vx.y), f2tf(vx.z), f2tf(vx.w));
        }
        __syncthreads();

        // S = Q K^T   [16 x 64] per warp
        float4 s[8];
        #pragma unroll
        for (int j = 0; j < 8; j++) s[j] = make_float4(0.f, 0.f, 0.f, 0.f);
        #pragma unroll
        for (int ks = 0; ks < 4; ks++) {
            #pragma unroll
            for (int j = 0; j < 8; j++) {
                int cn = j * 8 + g;
                uint32_t bf[2] = { Ks[cn * 36 + ks * 8 + tg], Ks[cn * 36 + ks * 8 + tg + 4] };
                mma8(s[j], qf[ks], bf);
            }
        }

        // mask: col valid iff col <= row + VKV && col < KVLEN
        #pragma unroll
        for (int j = 0; j < 8; j++) {
            int c0 = kv0 + j * 8 + 2 * tg;
            int c1 = c0 + 1;
            s[j].x = (c0 <= row_lo + VKV && c0 < KVLEN) ? s[j].x : -INFINITY;
            s[j].y = (c1 <= row_lo + VKV && c1 < KVLEN) ? s[j].y : -INFINITY;
            s[j].z = (c0 <= row_hi + VKV && c0 < KVLEN) ? s[j].z : -INFINITY;
            s[j].w = (c1 <= row_hi + VKV && c1 < KVLEN) ? s[j].w : -INFINITY;
        }

        // online softmax (rows g and g+8)
        float mx_lo = -INFINITY, mx_hi = -INFINITY;
        #pragma unroll
        for (int j = 0; j < 8; j++) {
            mx_lo = fmaxf(mx_lo, fmaxf(s[j].x, s[j].y));
            mx_hi = fmaxf(mx_hi, fmaxf(s[j].z, s[j].w));
        }
        mx_lo = fmaxf(mx_lo, __shfl_xor_sync(0xFFFFFFFFu, mx_lo, 1));
        mx_lo = fmaxf(mx_lo, __shfl_xor_sync(0xFFFFFFFFu, mx_lo, 2));
        mx_hi = fmaxf(mx_hi, __shfl_xor_sync(0xFFFFFFFFu, mx_hi, 1));
        mx_hi = fmaxf(mx_hi, __shfl_xor_sync(0xFFFFFFFFu, mx_hi, 2));
        float mn_lo = fmaxf(m_lo, mx_lo);
        float mn_hi = fmaxf(m_hi, mx_hi);
        float corr_lo = __expf(m_lo - mn_lo);
        float corr_hi = __expf(m_hi - mn_hi);

        float ps_lo = 0.f, ps_hi = 0.f;
        #pragma unroll
        for (int j = 0; j < 8; j++) {
            s[j].x = __expf(s[j].x - mn_lo);
            s[j].y = __expf(s[j].y - mn_lo);
            s[j].z = __expf(s[j].z - mn_hi);
            s[j].w = __expf(s[j].w - mn_hi);
            ps_lo += s[j].x + s[j].y;
            ps_hi += s[j].z + s[j].w;
        }
        ps_lo += __shfl_xor_sync(0xFFFFFFFFu, ps_lo, 1);
        ps_lo += __shfl_xor_sync(0xFFFFFFFFu, ps_lo, 2);
        ps_hi += __shfl_xor_sync(0xFFFFFFFFu, ps_hi, 1);
        ps_hi += __shfl_xor_sync(0xFFFFFFFFu, ps_hi, 2);
        l_lo = l_lo * corr_lo + ps_lo;
        l_hi = l_hi * corr_hi + ps_hi;
        m_lo = mn_lo; m_hi = mn_hi;
        #pragma unroll
        for (int j = 0; j < 8; j++) {
            z[j].x *= corr_lo; z[j].y *= corr_lo;
            z[j].z *= corr_hi; z[j].w *= corr_hi;
        }

        // P -> smem (warp-private region, tf32)
        uint32_t* Pw = Ps + (w * 16) * 68;
        #pragma unroll
        for (int j = 0; j < 8; j++) {
            int col = j * 8 + 2 * tg;
            Pw[(size_t)g * 68 + col]           = f2tf(s[j].x);
            Pw[(size_t)g * 68 + col + 1]       = f2tf(s[j].y);
            Pw[(size_t)(g + 8) * 68 + col]     = f2tf(s[j].z);
            Pw[(size_t)(g + 8) * 68 + col + 1] = f2tf(s[j].w);
        }
        __syncwarp();

        // Z += P V   (A = P [16x64], B = V [64x64])
        #pragma unroll
        for (int ks = 0; ks < 8; ks++) {
            uint32_t af[4];
            af[0] = Pw[(size_t)g       * 68 + ks * 8 + tg];
            af[1] = Pw[(size_t)(g + 8) * 68 + ks * 8 + tg];
            af[2] = Pw[(size_t)g       * 68 + ks * 8 + tg + 4];
            af[3] = Pw[(size_t)(g + 8) * 68 + ks * 8 + tg + 4];
            #pragma unroll
            for (int j = 0; j < 8; j++) {
                int cn = j * 8 + g;
                uint32_t bf[2] = { Vs[(ks * 8 + tg) * 72 + cn], Vs[(ks * 8 + tg + 4) * 72 + cn] };
                mma8(z[j], af, bf);
            }
        }
    }

    float li_lo = 1.f / l_lo;
    float li_hi = 1.f / l_hi;
    float* zlo = g_z + ((size_t)b * SEQ + row_lo) * NOV + h * RATIO;
    float* zhi = g_z + ((size_t)b * SEQ + row_hi) * NOV + h * RATIO;
    #pragma unroll
    for (int j = 0; j < 8; j++) {
        int col = j * 8 + 2 * tg;
        *(float2*)&zlo[col] = make_float2(z[j].x * li_lo, z[j].y * li_lo);
        *(float2*)&zhi[col] = make_float2(z[j].z * li_hi, z[j].w * li_hi);
    }
}

// ---------------- output (tf32 mma, NN): BM=128, BN=64, grid 16x16 ----------------
__global__ void __launch_bounds__(256) out_gemm_kernel(
    const float* __restrict__ Wo, float* __restrict__ out)
{
    __shared__ uint32_t As[128][36];
    __shared__ uint32_t Bs2[32][68];
    int n0 = blockIdx.x * 64, r0 = blockIdx.y * 128;
    int t = threadIdx.x;
    int w = t >> 5, lane = t & 31;
    int g = lane >> 2, tg = lane & 3;
    int wm = w >> 1, wn = w & 1;

    float4 acc[2][4];
    #pragma unroll
    for (int i = 0; i < 2; i++)
        #pragma unroll
        for (int j = 0; j < 4; j++) acc[i][j] = make_float4(0.f, 0.f, 0.f, 0.f);

    for (int k0 = 0; k0 < NOV; k0 += 32) {
        #pragma unroll
        for (int i = 0; i < 4; i++) {
            int idx = t + i * 256;
            int row = idx >> 3, kq = (idx & 7) << 2;
            float4 a = *(const float4*)(g_z + (size_t)(r0 + row) * NOV + k0 + kq);
            *(uint4*)&As[row][kq] = make_uint4(f2tf(a.x), f2tf(a.y), f2tf(a.z), f2tf(a.w));
        }
        #pragma unroll
        for (int i = 0; i < 2; i++) {
            int idx = t + i * 256;
            int kk = idx >> 4, nq = (idx & 15) << 2;
            float4 bx = *(const float4*)(Wo + (size_t)(k0 + kk) * DMODEL + n0 + nq);
            *(uint4*)&Bs2[kk][nq] = make_uint4(f2tf(bx.x), f2tf(bx.y), f2tf(bx.z), f2tf(bx.w));
        }
        __syncthreads();
        #pragma unroll
        for (int ks = 0; ks < 32; ks += 8) {
            uint32_t af[2][4];
            #pragma unroll
            for (int i = 0; i < 2; i++) {
                int rm = wm * 32 + i * 16;
                af[i][0] = As[rm + g    ][ks + tg];
                af[i][1] = As[rm + g + 8][ks + tg];
                af[i][2] = As[rm + g    ][ks + tg + 4];
                af[i][3] = As[rm + g + 8][ks + tg + 4];
            }
            #pragma unroll
            for (int j = 0; j < 4; j++) {
                int cn = wn * 32 + j * 8 + g;
                uint32_t bf[2] = { Bs2[ks + tg][cn], Bs2[ks + tg + 4][cn] };
                mma8(acc[0][j], af[0], bf);
                mma8(acc[1][j], af[1], bf);
            }
        }
        __syncthreads();
    }

    #pragma unroll
    for (int i = 0; i < 2; i++) {
        int row0 = r0 + wm * 32 + i * 16 + g;
        #pragma unroll
        for (int j = 0; j < 4; j++) {
            int n = n0 + wn * 32 + j * 8 + tg * 2;
            *(float2*)&out[(size_t)row0 * DMODEL + n] = make_float2(acc[i][j].x, acc[i][j].y);
            *(float2*)&out[(size_t)(row0 + 8) * DMODEL + n] = make_float2(acc[i][j].z, acc[i][j].w);
        }
    }
}

// ---------------- launch ----------------
extern "C" void kernel_launch(void* const* d_in, const int* in_sizes, int n_in,
                              void* d_out, int out_size)
{
    const float* resid = (const float*)d_in[0];
    const float* Wq    = (const float*)d_in[1];
    const float* Wk    = (const float*)d_in[2];
    const float* Wv    = (const float*)d_in[3];
    const float* Wo    = (const float*)d_in[4];
    const float* bq    = (const float*)d_in[5];
    const float* bk    = (const float*)d_in[6];
    const float* bv    = (const float*)d_in[7];
    const float* vk    = (const float*)d_in[8];
    const float* vv    = (const float*)d_in[9];
    float* out = (float*)d_out;

    static int attn_smem_set = 0;
    const int ATTN_SMEM = (64 * 36 + 64 * 72 + 128 * 68) * 4;  // 62464
    if (!attn_smem_set) {
        cudaFuncSetAttribute(attn_mma_kernel,
                             cudaFuncAttributeMaxDynamicSharedMemorySize, ATTN_SMEM);
        attn_smem_set = 1;
    }

    rot_init_kernel<<<64, 256>>>();
    copy_virtual_kernel<<<256, 256>>>(vk, vv);
    proj_qk_kernel<<<dim3(16, 32), 256>>>(resid, Wq, Wk, bq, bk);
    proj_v_kernel<<<dim3(16, 16), 256>>>(resid, Wv, bv);
    attn_mma_kernel<<<dim3(8, 32, 2), 256, ATTN_SMEM>>>();
    out_gemm_kernel<<<dim3(16, 16), 256>>>(Wo, out);
}

// round 6
// speedup vs baseline: 5.9455x; 1.0956x over previous
#include <cuda_runtime.h>
#include <math.h>
#include <stdint.h>

#define SEQ    1024
#define DMODEL 1024
#define NQK    32
#define DQK    32
#define NOV    2048
#define BATCH  2
#define VKV    16
#define KVLEN  (SEQ + VKV)   /* 1040 */
#define RATIO  (NOV / NQK)   /* 64 */

// ---------------- scratch (static device globals; no allocation) ----------------
__device__ float g_q   [(size_t)BATCH * NQK * SEQ   * DQK];   // [b][h][s][d]  (pre-scaled by 1/sqrt(32))
__device__ float g_kext[(size_t)BATCH * NQK * KVLEN * DQK];   // [b][h][j][d]
__device__ float g_vext[(size_t)BATCH * KVLEN * NOV];         // [b][j][n]
__device__ float g_z   [(size_t)BATCH * SEQ * NOV];           // [bs][n]
__device__ float g_sin [SEQ * 16];
__device__ float g_cos [SEQ * 16];

// ---------------- tf32 mma helpers ----------------
__device__ __forceinline__ uint32_t f2tf(float x) {
    uint32_t y;
    asm("cvt.rna.tf32.f32 %0, %1;" : "=r"(y) : "f"(x));
    return y;
}

__device__ __forceinline__ void mma8(float4& d, const uint32_t* a, const uint32_t* b) {
    asm volatile(
        "mma.sync.aligned.m16n8k8.row.col.f32.tf32.tf32.f32 "
        "{%0,%1,%2,%3}, {%4,%5,%6,%7}, {%8,%9}, {%0,%1,%2,%3};\n"
        : "+f"(d.x), "+f"(d.y), "+f"(d.z), "+f"(d.w)
        : "r"(a[0]), "r"(a[1]), "r"(a[2]), "r"(a[3]), "r"(b[0]), "r"(b[1]));
}

// ---------------- rotary table ----------------
__global__ void rot_init_kernel() {
    int i = blockIdx.x * blockDim.x + threadIdx.x;
    if (i >= SEQ * 16) return;
    int pos = i >> 4, jm = i & 15;
    float freq = powf(10000.0f, (float)jm * (1.0f / 16.0f));
    float ang = (float)pos / freq;
    g_sin[i] = sinf(ang);
    g_cos[i] = cosf(ang);
}

// ---------------- append virtual k/v ----------------
__global__ void copy_virtual_kernel(const float* __restrict__ vk,
                                    const float* __restrict__ vv)
{
    int i = blockIdx.x * blockDim.x + threadIdx.x;
    if (i < BATCH * NQK * VKV * DQK) {
        int d  = i & 31;
        int tt = (i >> 5) & 15;
        int h  = (i >> 9) & 31;
        int b  = i >> 14;
        g_kext[(((size_t)b * NQK + h) * KVLEN + SEQ + tt) * DQK + d] =
            vk[((size_t)tt * NQK + h) * DQK + d];
    }
    if (i < BATCH * VKV * NOV) {
        int n  = i & 2047;
        int tt = (i >> 11) & 15;
        int b  = i >> 15;
        g_vext[((size_t)b * KVLEN + SEQ + tt) * NOV + n] = vv[(size_t)tt * NOV + n];
    }
}

// ---------------- fused QKV projection GEMM (tf32 mma, pipelined) ----------------
// Combined N = 4096: n-tiles 0..7 -> Q (1024 cols), 8..15 -> K, 16..31 -> V (2048 cols).
// BM=128, BN=128, BK=32, 8 warps (4 wm x 2 wn), warp tile 32x64.
// Double-buffered smem + register prefetch, ONE syncthreads per k-iter.
// Epilogue: V direct (+bias); Q/K stage in smem (aliases pipeline bufs), rotary+bias(+scale).
__global__ void __launch_bounds__(256) qkv_gemm_kernel(
    const float* __restrict__ resid, const float* __restrict__ Wq,
    const float* __restrict__ Wk, const float* __restrict__ Wv,
    const float* __restrict__ bq, const float* __restrict__ bk,
    const float* __restrict__ bv)
{
    extern __shared__ uint32_t dsm[];            // 73728 B
    uint32_t* As0 = dsm;                         // [2][128][36]
    uint32_t* Bs0 = dsm + 2 * 128 * 36;          // [2][128][36]
    float (*Cs)[132] = (float(*)[132])dsm;       // aliases (used after mainloop)

    int nt = blockIdx.x;
    int n0 = nt * 128;
    int r0 = blockIdx.y * 128;
    int region = (nt < 8) ? 0 : (nt < 16) ? 1 : 2;   // 0=q, 1=k, 2=v
    const float* Wqk = (region == 0) ? Wq : Wk;
    int cb = (region == 0) ? n0 : n0 - 1024;          // col base within q/k (0..1023)
    int hbase = cb >> 5;
    const float* Bv = Wv + (size_t)(n0 - 2048) * DMODEL;

    int t = threadIdx.x, w = t >> 5, lane = t & 31;
    int g = lane >> 2, tg = lane & 3;
    int wm = w >> 1, wn = w & 1;

    float4 acc[2][8];
    #pragma unroll
    for (int i = 0; i < 2; i++)
        #pragma unroll
        for (int j = 0; j < 8; j++) acc[i][j] = make_float4(0.f, 0.f, 0.f, 0.f);

    float4 ra[4], rb[4];

    // ---- prefetch chunk 0 ----
    #pragma unroll
    for (int i = 0; i < 4; i++) {
        int idx = t + i * 256;
        int row = idx >> 3, kq = (idx & 7) << 2;
        ra[i] = *(const float4*)(resid + (size_t)(r0 + row) * DMODEL + kq);
    }
    if (region < 2) {
        #pragma unroll
        for (int i = 0; i < 4; i++) {
            int idx = t + i * 256;
            int h = idx >> 8, kk = (idx >> 3) & 31, d4 = (idx & 7) << 2;
            rb[i] = *(const float4*)(Wqk + (size_t)(hbase + h) * DMODEL * DQK
                                     + (size_t)kk * DQK + d4);
        }
    } else {
        #pragma unroll
        for (int i = 0; i < 4; i++) {
            int idx = t + i * 256;
            int row = idx >> 3, kq = (idx & 7) << 2;
            rb[i] = *(const float4*)(Bv + (size_t)row * DMODEL + kq);
        }
    }

    for (int kt = 0; kt < 32; kt++) {
        int buf = kt & 1;
        uint32_t* A = As0 + buf * (128 * 36);
        uint32_t* B = Bs0 + buf * (128 * 36);

        // ---- STS current chunk ----
        #pragma unroll
        for (int i = 0; i < 4; i++) {
            int idx = t + i * 256;
            int row = idx >> 3, kq = (idx & 7) << 2;
            *(uint4*)&A[row * 36 + kq] =
                make_uint4(f2tf(ra[i].x), f2tf(ra[i].y), f2tf(ra[i].z), f2tf(ra[i].w));
        }
        if (region < 2) {
            #pragma unroll
            for (int i = 0; i < 4; i++) {
                int idx = t + i * 256;
                int h = idx >> 8, kk = (idx >> 3) & 31, d4 = (idx & 7) << 2;
                int nn = h * 32 + d4;
                B[(nn    ) * 36 + kk] = f2tf(rb[i].x);
                B[(nn + 1) * 36 + kk] = f2tf(rb[i].y);
                B[(nn + 2) * 36 + kk] = f2tf(rb[i].z);
                B[(nn + 3) * 36 + kk] = f2tf(rb[i].w);
            }
        } else {
            #pragma unroll
            for (int i = 0; i < 4; i++) {
                int idx = t + i * 256;
                int row = idx >> 3, kq = (idx & 7) << 2;
                *(uint4*)&B[row * 36 + kq] =
                    make_uint4(f2tf(rb[i].x), f2tf(rb[i].y), f2tf(rb[i].z), f2tf(rb[i].w));
            }
        }
        __syncthreads();

        // ---- prefetch next chunk ----
        if (kt < 31) {
            int k0 = (kt + 1) * 32;
            #pragma unroll
            for (int i = 0; i < 4; i++) {
                int idx = t + i * 256;
                int row = idx >> 3, kq = (idx & 7) << 2;
                ra[i] = *(const float4*)(resid + (size_t)(r0 + row) * DMODEL + k0 + kq);
            }
            if (region < 2) {
                #pragma unroll
                for (int i = 0; i < 4; i++) {
                    int idx = t + i * 256;
                    int h = idx >> 8, kk = (idx >> 3) & 31, d4 = (idx & 7) << 2;
                    rb[i] = *(const float4*)(Wqk + (size_t)(hbase + h) * DMODEL * DQK
                                             + (size_t)(k0 + kk) * DQK + d4);
                }
            } else {
                #pragma unroll
                for (int i = 0; i < 4; i++) {
                    int idx = t + i * 256;
                    int row = idx >> 3, kq = (idx & 7) << 2;
                    rb[i] = *(const float4*)(Bv + (size_t)row * DMODEL + k0 + kq);
                }
            }
        }

        // ---- MMA on current buffer ----
        #pragma unroll
        for (int ks = 0; ks < 32; ks += 8) {
            uint32_t af[2][4];
            #pragma unroll
            for (int i = 0; i < 2; i++) {
                int rm = wm * 32 + i * 16;
                af[i][0] = A[(rm + g    ) * 36 + ks + tg];
                af[i][1] = A[(rm + g + 8) * 36 + ks + tg];
                af[i][2] = A[(rm + g    ) * 36 + ks + tg + 4];
                af[i][3] = A[(rm + g + 8) * 36 + ks + tg + 4];
            }
            #pragma unroll
            for (int j = 0; j < 8; j++) {
                int cn = wn * 64 + j * 8 + g;
                uint32_t bf[2] = { B[cn * 36 + ks + tg], B[cn * 36 + ks + tg + 4] };
                mma8(acc[0][j], af[0], bf);
                mma8(acc[1][j], af[1], bf);
            }
        }
        // single sync per iter (next STS targets the other buffer; see analysis)
    }

    if (region == 2) {
        // ---- V epilogue: direct write + bias ----
        int nv0 = n0 - 2048;
        #pragma unroll
        for (int i = 0; i < 2; i++) {
            int row0 = r0 + wm * 32 + i * 16 + g;
            #pragma unroll
            for (int j = 0; j < 8; j++) {
                int n = nv0 + wn * 64 + j * 8 + tg * 2;
                float2 bvv = *(const float2*)(bv + n);
                int b1 = row0 >> 10, s1 = row0 & 1023;
                *(float2*)&g_vext[((size_t)b1 * KVLEN + s1) * NOV + n] =
                    make_float2(acc[i][j].x + bvv.x, acc[i][j].y + bvv.y);
                int r2 = row0 + 8;
                int b2 = r2 >> 10, s2 = r2 & 1023;
                *(float2*)&g_vext[((size_t)b2 * KVLEN + s2) * NOV + n] =
                    make_float2(acc[i][j].z + bvv.x, acc[i][j].w + bvv.y);
            }
        }
    } else {
        // ---- Q/K epilogue: stage + bias, then rotary scatter ----
        __syncthreads();   // all mma reads done; Cs aliases pipeline smem
        const float* bias = (region == 0) ? bq : bk;
        #pragma unroll
        for (int i = 0; i < 2; i++) {
            int rr = wm * 32 + i * 16 + g;
            #pragma unroll
            for (int j = 0; j < 8; j++) {
                int c = wn * 64 + j * 8 + tg * 2;
                float b0 = bias[cb + c];
                float b1 = bias[cb + c + 1];
                Cs[rr    ][c    ] = acc[i][j].x + b0;
                Cs[rr    ][c + 1] = acc[i][j].y + b1;
                Cs[rr + 8][c    ] = acc[i][j].z + b0;
                Cs[rr + 8][c + 1] = acc[i][j].w + b1;
            }
        }
        __syncthreads();

        const float invscale = 0.17677669529663687f;   // 1/sqrt(32)
        float sc = (region == 0) ? invscale : 1.f;
        #pragma unroll
        for (int p = 0; p < 2; p++) {
            int idx = t + p * 256;          // 512 (row, head) pairs
            int r = idx >> 2, hh = idx & 3;
            int grow = r0 + r;
            int bb = grow >> 10, pos = grow & 1023;
            int h = hbase + hh;
            const float* base = &Cs[r][hh * 32];
            float* dst = (region == 0)
                ? g_q    + (((size_t)bb * NQK + h) * SEQ   + pos) * DQK
                : g_kext + (((size_t)bb * NQK + h) * KVLEN + pos) * DQK;
            #pragma unroll
            for (int c = 0; c < 32; c++) {
                float val  = base[c];
                float flip = (c < 16) ? -base[c + 16] : base[c - 16];
                int jm = c & 15;
                float sn = g_sin[pos * 16 + jm];
                float cs = g_cos[pos * 16 + jm];
                dst[c] = (val * cs + flip * sn) * sc;
            }
        }
    }
}

// ---------------- attention: tf32 mma flash (unchanged from R4) ----------------
__global__ void __launch_bounds__(256) attn_mma_kernel()
{
    extern __shared__ uint32_t smem[];
    uint32_t* Ks = smem;                       // pitch 36
    uint32_t* Vs = smem + 64 * 36;             // pitch 72
    uint32_t* Ps = smem + 64 * 36 + 64 * 72;   // pitch 68

    int qt = blockIdx.x, h = blockIdx.y, b = blockIdx.z;
    int i0 = qt * 128;
    int t = threadIdx.x, w = t >> 5, lane = t & 31;
    int g = lane >> 2, tg = lane & 3;

    uint32_t qf[4][4];
    {
        const float* qbase = g_q + (((size_t)b * NQK + h) * SEQ + i0 + w * 16) * DQK;
        #pragma unroll
        for (int kb = 0; kb < 4; kb++) {
            qf[kb][0] = f2tf(qbase[(size_t)g       * DQK + kb * 8 + tg]);
            qf[kb][1] = f2tf(qbase[(size_t)(g + 8) * DQK + kb * 8 + tg]);
            qf[kb][2] = f2tf(qbase[(size_t)g       * DQK + kb * 8 + tg + 4]);
            qf[kb][3] = f2tf(qbase[(size_t)(g + 8) * DQK + kb * 8 + tg + 4]);
        }
    }

    float m_lo = -INFINITY, m_hi = -INFINITY, l_lo = 0.f, l_hi = 0.f;
    float4 z[8];
    #pragma unroll
    for (int j = 0; j < 8; j++) z[j] = make_float4(0.f, 0.f, 0.f, 0.f);

    int row_lo = i0 + w * 16 + g;
    int row_hi = row_lo + 8;

    int jlim = i0 + 128 + VKV;
    if (jlim > KVLEN) jlim = KVLEN;
    int nch = (jlim + 63) >> 6;

    const float* kbp = g_kext + ((size_t)b * NQK + h) * KVLEN * DQK;
    const float* vbp = g_vext + (size_t)b * KVLEN * NOV + h * RATIO;

    for (int ch = 0; ch < nch; ch++) {
        int kv0 = ch << 6;
        __syncthreads();
        #pragma unroll
        for (int i = 0; i < 2; i++) {
            int idx = t + i * 256;
            int row = idx >> 3, c4 = (idx & 7) << 2;
            int gj = kv0 + row;
            float4 kx = (gj < KVLEN) ? *(const float4*)(kbp + (size_t)gj * DQK + c4)
                                     : make_float4(0.f, 0.f, 0.f, 0.f);
            *(uint4*)&Ks[row * 36 + c4] = make_uint4(f2tf(kx.x), f2tf(kx.y), f2tf(kx.z), f2tf(kx.w));
        }
        #pragma unroll
        for (int i = 0; i < 4; i++) {
            int idx = t + i * 256;
            int row = idx >> 4, c4 = (idx & 15) << 2;
            int gj = kv0 + row;
            float4 vx = (gj < KVLEN) ? *(const float4*)(vbp + (size_t)gj * NOV + c4)
                                     : make_float4(0.f, 0.f, 0.f, 0.f);
            *(uint4*)&Vs[row * 72 + c4] = make_uint4(f2tf(vx.x), f2tf(vx.y), f2tf(vx.z), f2tf(vx.w));
        }
        __syncthreads();

        float4 s[8];
        #pragma unroll
        for (int j = 0; j < 8; j++) s[j] = make_float4(0.f, 0.f, 0.f, 0.f);
        #pragma unroll
        for (int ks = 0; ks < 4; ks++) {
            #pragma unroll
            for (int j = 0; j < 8; j++) {
                int cn = j * 8 + g;
                uint32_t bf[2] = { Ks[cn * 36 + ks * 8 + tg], Ks[cn * 36 + ks * 8 + tg + 4] };
                mma8(s[j], qf[ks], bf);
            }
        }

        #pragma unroll
        for (int j = 0; j < 8; j++) {
            int c0 = kv0 + j * 8 + 2 * tg;
            int c1 = c0 + 1;
            s[j].x = (c0 <= row_lo + VKV && c0 < KVLEN) ? s[j].x : -INFINITY;
            s[j].y = (c1 <= row_lo + VKV && c1 < KVLEN) ? s[j].y : -INFINITY;
            s[j].z = (c0 <= row_hi + VKV && c0 < KVLEN) ? s[j].z : -INFINITY;
            s[j].w = (c1 <= row_hi + VKV && c1 < KVLEN) ? s[j].w : -INFINITY;
        }

        float mx_lo = -INFINITY, mx_hi = -INFINITY;
        #pragma unroll
        for (int j = 0; j < 8; j++) {
            mx_lo = fmaxf(mx_lo, fmaxf(s[j].x, s[j].y));
            mx_hi = fmaxf(mx_hi, fmaxf(s[j].z, s[j].w));
        }
        mx_lo = fmaxf(mx_lo, __shfl_xor_sync(0xFFFFFFFFu, mx_lo, 1));
        mx_lo = fmaxf(mx_lo, __shfl_xor_sync(0xFFFFFFFFu, mx_lo, 2));
        mx_hi = fmaxf(mx_hi, __shfl_xor_sync(0xFFFFFFFFu, mx_hi, 1));
        mx_hi = fmaxf(mx_hi, __shfl_xor_sync(0xFFFFFFFFu, mx_hi, 2));
        float mn_lo = fmaxf(m_lo, mx_lo);
        float mn_hi = fmaxf(m_hi, mx_hi);
        float corr_lo = __expf(m_lo - mn_lo);
        float corr_hi = __expf(m_hi - mn_hi);

        float ps_lo = 0.f, ps_hi = 0.f;
        #pragma unroll
        for (int j = 0; j < 8; j++) {
            s[j].x = __expf(s[j].x - mn_lo);
            s[j].y = __expf(s[j].y - mn_lo);
            s[j].z = __expf(s[j].z - mn_hi);
            s[j].w = __expf(s[j].w - mn_hi);
            ps_lo += s[j].x + s[j].y;
            ps_hi += s[j].z + s[j].w;
        }
        ps_lo += __shfl_xor_sync(0xFFFFFFFFu, ps_lo, 1);
        ps_lo += __shfl_xor_sync(0xFFFFFFFFu, ps_lo, 2);
        ps_hi += __shfl_xor_sync(0xFFFFFFFFu, ps_hi, 1);
        ps_hi += __shfl_xor_sync(0xFFFFFFFFu, ps_hi, 2);
        l_lo = l_lo * corr_lo + ps_lo;
        l_hi = l_hi * corr_hi + ps_hi;
        m_lo = mn_lo; m_hi = mn_hi;
        #pragma unroll
        for (int j = 0; j < 8; j++) {
            z[j].x *= corr_lo; z[j].y *= corr_lo;
            z[j].z *= corr_hi; z[j].w *= corr_hi;
        }

        uint32_t* Pw = Ps + (w * 16) * 68;
        #pragma unroll
        for (int j = 0; j < 8; j++) {
            int col = j * 8 + 2 * tg;
            Pw[(size_t)g * 68 + col]           = f2tf(s[j].x);
            Pw[(size_t)g * 68 + col + 1]       = f2tf(s[j].y);
            Pw[(size_t)(g + 8) * 68 + col]     = f2tf(s[j].z);
            Pw[(size_t)(g + 8) * 68 + col + 1] = f2tf(s[j].w);
        }
        __syncwarp();

        #pragma unroll
        for (int ks = 0; ks < 8; ks++) {
            uint32_t af[4];
            af[0] = Pw[(size_t)g       * 68 + ks * 8 + tg];
            af[1] = Pw[(size_t)(g + 8) * 68 + ks * 8 + tg];
            af[2] = Pw[(size_t)g       * 68 + ks * 8 + tg + 4];
            af[3] = Pw[(size_t)(g + 8) * 68 + ks * 8 + tg + 4];
            #pragma unroll
            for (int j = 0; j < 8; j++) {
                int cn = j * 8 + g;
                uint32_t bf[2] = { Vs[(ks * 8 + tg) * 72 + cn], Vs[(ks * 8 + tg + 4) * 72 + cn] };
                mma8(z[j], af, bf);
            }
        }
    }

    float li_lo = 1.f / l_lo;
    float li_hi = 1.f / l_hi;
    float* zlo = g_z + ((size_t)b * SEQ + row_lo) * NOV + h * RATIO;
    float* zhi = g_z + ((size_t)b * SEQ + row_hi) * NOV + h * RATIO;
    #pragma unroll
    for (int j = 0; j < 8; j++) {
        int col = j * 8 + 2 * tg;
        *(float2*)&zlo[col] = make_float2(z[j].x * li_lo, z[j].y * li_lo);
        *(float2*)&zhi[col] = make_float2(z[j].z * li_hi, z[j].w * li_hi);
    }
}

// ---------------- output GEMM (tf32 mma, NN, pipelined): BM=128, BN=64 ----------------
__global__ void __launch_bounds__(256) out_gemm_kernel(
    const float* __restrict__ Wo, float* __restrict__ out)
{
    extern __shared__ uint32_t dsm[];
    uint32_t* As0 = dsm;                  // [2][128][36]
    uint32_t* Bs0 = dsm + 2 * 128 * 36;   // [2][32][68]

    int n0 = blockIdx.x * 64, r0 = blockIdx.y * 128;
    int t = threadIdx.x;
    int w = t >> 5, lane = t & 31;
    int g = lane >> 2, tg = lane & 3;
    int wm = w >> 1, wn = w & 1;

    float4 acc[2][4];
    #pragma unroll
    for (int i = 0; i < 2; i++)
        #pragma unroll
        for (int j = 0; j < 4; j++) acc[i][j] = make_float4(0.f, 0.f, 0.f, 0.f);

    float4 ra[4], rb[2];
    #pragma unroll
    for (int i = 0; i < 4; i++) {
        int idx = t + i * 256;
        int row = idx >> 3, kq = (idx & 7) << 2;
        ra[i] = *(const float4*)(g_z + (size_t)(r0 + row) * NOV + kq);
    }
    #pragma unroll
    for (int i = 0; i < 2; i++) {
        int idx = t + i * 256;
        int kk = idx >> 4, nq = (idx & 15) << 2;
        rb[i] = *(const float4*)(Wo + (size_t)kk * DMODEL + n0 + nq);
    }

    for (int kt = 0; kt < 64; kt++) {
        int buf = kt & 1;
        uint32_t* A = As0 + buf * (128 * 36);
        uint32_t* B = Bs0 + buf * (32 * 68);

        #pragma unroll
        for (int i = 0; i < 4; i++) {
            int idx = t + i * 256;
            int row = idx >> 3, kq = (idx & 7) << 2;
            *(uint4*)&A[row * 36 + kq] =
                make_uint4(f2tf(ra[i].x), f2tf(ra[i].y), f2tf(ra[i].z), f2tf(ra[i].w));
        }
        #pragma unroll
        for (int i = 0; i < 2; i++) {
            int idx = t + i * 256;
            int kk = idx >> 4, nq = (idx & 15) << 2;
            *(uint4*)&B[kk * 68 + nq] =
                make_uint4(f2tf(rb[i].x), f2tf(rb[i].y), f2tf(rb[i].z), f2tf(rb[i].w));
        }
        __syncthreads();

        if (kt < 63) {
            int k0 = (kt + 1) * 32;
            #pragma unroll
            for (int i = 0; i < 4; i++) {
                int idx = t + i * 256;
                int row = idx >> 3, kq = (idx & 7) << 2;
                ra[i] = *(const float4*)(g_z + (size_t)(r0 + row) * NOV + k0 + kq);
            }
            #pragma unroll
            for (int i = 0; i < 2; i++) {
                int idx = t + i * 256;
                int kk = idx >> 4, nq = (idx & 15) << 2;
                rb[i] = *(const float4*)(Wo + (size_t)(k0 + kk) * DMODEL + n0 + nq);
            }
        }

        #pragma unroll
        for (int ks = 0; ks < 32; ks += 8) {
            uint32_t af[2][4];
            #pragma unroll
            for (int i = 0; i < 2; i++) {
                int rm = wm * 32 + i * 16;
                af[i][0] = A[(rm + g    ) * 36 + ks + tg];
                af[i][1] = A[(rm + g + 8) * 36 + ks + tg];
                af[i][2] = A[(rm + g    ) * 36 + ks + tg + 4];
                af[i][3] = A[(rm + g + 8) * 36 + ks + tg + 4];
            }
            #pragma unroll
            for (int j = 0; j < 4; j++) {
                int cn = wn * 32 + j * 8 + g;
                uint32_t bf[2] = { B[(ks + tg) * 68 + cn], B[(ks + tg + 4) * 68 + cn] };
                mma8(acc[0][j], af[0], bf);
                mma8(acc[1][j], af[1], bf);
            }
        }
    }

    #pragma unroll
    for (int i = 0; i < 2; i++) {
        int row0 = r0 + wm * 32 + i * 16 + g;
        #pragma unroll
        for (int j = 0; j < 4; j++) {
            int n = n0 + wn * 32 + j * 8 + tg * 2;
            *(float2*)&out[(size_t)row0 * DMODEL + n] = make_float2(acc[i][j].x, acc[i][j].y);
            *(float2*)&out[(size_t)(row0 + 8) * DMODEL + n] = make_float2(acc[i][j].z, acc[i][j].w);
        }
    }
}

// ---------------- launch ----------------
extern "C" void kernel_launch(void* const* d_in, const int* in_sizes, int n_in,
                              void* d_out, int out_size)
{
    const float* resid = (const float*)d_in[0];
    const float* Wq    = (const float*)d_in[1];
    const float* Wk    = (const float*)d_in[2];
    const float* Wv    = (const float*)d_in[3];
    const float* Wo    = (const float*)d_in[4];
    const float* bq    = (const float*)d_in[5];
    const float* bk    = (const float*)d_in[6];
    const float* bv    = (const float*)d_in[7];
    const float* vk    = (const float*)d_in[8];
    const float* vv    = (const float*)d_in[9];
    float* out = (float*)d_out;

    const int ATTN_SMEM = (64 * 36 + 64 * 72 + 128 * 68) * 4;   // 62464
    const int QKV_SMEM  = (2 * 128 * 36 + 2 * 128 * 36) * 4;    // 73728
    const int OUT_SMEM  = (2 * 128 * 36 + 2 * 32 * 68) * 4;     // 54272
    static int smem_set = 0;
    if (!smem_set) {
        cudaFuncSetAttribute(attn_mma_kernel,
                             cudaFuncAttributeMaxDynamicSharedMemorySize, ATTN_SMEM);
        cudaFuncSetAttribute(qkv_gemm_kernel,
                             cudaFuncAttributeMaxDynamicSharedMemorySize, QKV_SMEM);
        cudaFuncSetAttribute(out_gemm_kernel,
                             cudaFuncAttributeMaxDynamicSharedMemorySize, OUT_SMEM);
        smem_set = 1;
    }

    rot_init_kernel<<<64, 256>>>();
    copy_virtual_kernel<<<256, 256>>>(vk, vv);
    qkv_gemm_kernel<<<dim3(32, 16), 256, QKV_SMEM>>>(resid, Wq, Wk, Wv, bq, bk, bv);
    attn_mma_kernel<<<dim3(8, 32, 2), 256, ATTN_SMEM>>>();
    out_gemm_kernel<<<dim3(16, 16), 256, OUT_SMEM>>>(Wo, out);
}

// round 7
// speedup vs baseline: 6.4109x; 1.0783x over previous
#include <cuda_runtime.h>
#include <math.h>
#include <stdint.h>

#define SEQ    1024
#define DMODEL 1024
#define NQK    32
#define DQK    32
#define NOV    2048
#define BATCH  2
#define VKV    16
#define KVLEN  (SEQ + VKV)   /* 1040 */
#define RATIO  (NOV / NQK)   /* 64 */
#define FULLM  0xFFFFFFFFu

// ---------------- scratch (static device globals; no allocation) ----------------
__device__ float g_q   [(size_t)BATCH * NQK * SEQ   * DQK];   // pre-scaled by 1/sqrt(32)
__device__ float g_kext[(size_t)BATCH * NQK * KVLEN * DQK];
__device__ float g_vext[(size_t)BATCH * KVLEN * NOV];
__device__ float g_z   [(size_t)BATCH * SEQ * NOV];
__device__ float g_sin [SEQ * 16];
__device__ float g_cos [SEQ * 16];

// ---------------- tf32 mma helpers ----------------
__device__ __forceinline__ uint32_t f2tf(float x) {
    uint32_t y;
    asm("cvt.rna.tf32.f32 %0, %1;" : "=r"(y) : "f"(x));
    return y;
}

__device__ __forceinline__ void mma8(float4& d, const uint32_t* a, const uint32_t* b) {
    asm volatile(
        "mma.sync.aligned.m16n8k8.row.col.f32.tf32.tf32.f32 "
        "{%0,%1,%2,%3}, {%4,%5,%6,%7}, {%8,%9}, {%0,%1,%2,%3};\n"
        : "+f"(d.x), "+f"(d.y), "+f"(d.z), "+f"(d.w)
        : "r"(a[0]), "r"(a[1]), "r"(a[2]), "r"(a[3]), "r"(b[0]), "r"(b[1]));
}

__device__ __forceinline__ void cp_async16(uint32_t dst_smem, const void* src, int src_bytes) {
    asm volatile("cp.async.cg.shared.global [%0], [%1], 16, %2;"
                 :: "r"(dst_smem), "l"(src), "r"(src_bytes));
}

// ---------------- rotary table ----------------
__global__ void rot_init_kernel() {
    int i = blockIdx.x * blockDim.x + threadIdx.x;
    if (i >= SEQ * 16) return;
    int pos = i >> 4, jm = i & 15;
    float freq = powf(10000.0f, (float)jm * (1.0f / 16.0f));
    float ang = (float)pos / freq;
    g_sin[i] = sinf(ang);
    g_cos[i] = cosf(ang);
}

// ---------------- append virtual k/v ----------------
__global__ void copy_virtual_kernel(const float* __restrict__ vk,
                                    const float* __restrict__ vv)
{
    int i = blockIdx.x * blockDim.x + threadIdx.x;
    if (i < BATCH * NQK * VKV * DQK) {
        int d  = i & 31;
        int tt = (i >> 5) & 15;
        int h  = (i >> 9) & 31;
        int b  = i >> 14;
        g_kext[(((size_t)b * NQK + h) * KVLEN + SEQ + tt) * DQK + d] =
            vk[((size_t)tt * NQK + h) * DQK + d];
    }
    if (i < BATCH * VKV * NOV) {
        int n  = i & 2047;
        int tt = (i >> 11) & 15;
        int b  = i >> 15;
        g_vext[((size_t)b * KVLEN + SEQ + tt) * NOV + n] = vv[(size_t)tt * NOV + n];
    }
}

// ---------------- fused QKV projection GEMM (tf32 mma, pipelined) ----------------
__global__ void __launch_bounds__(256) qkv_gemm_kernel(
    const float* __restrict__ resid, const float* __restrict__ Wq,
    const float* __restrict__ Wk, const float* __restrict__ Wv,
    const float* __restrict__ bq, const float* __restrict__ bk,
    const float* __restrict__ bv)
{
    extern __shared__ uint32_t dsm[];            // 73728 B
    uint32_t* As0 = dsm;                         // [2][128][36]
    uint32_t* Bs0 = dsm + 2 * 128 * 36;          // [2][128][36]
    float (*Cs)[132] = (float(*)[132])dsm;       // aliases (used after mainloop)

    int nt = blockIdx.x;
    int n0 = nt * 128;
    int r0 = blockIdx.y * 128;
    int region = (nt < 8) ? 0 : (nt < 16) ? 1 : 2;
    const float* Wqk = (region == 0) ? Wq : Wk;
    int cb = (region == 0) ? n0 : n0 - 1024;
    int hbase = cb >> 5;
    const float* Bv = Wv + (size_t)(n0 - 2048) * DMODEL;

    int t = threadIdx.x, w = t >> 5, lane = t & 31;
    int g = lane >> 2, tg = lane & 3;
    int wm = w >> 1, wn = w & 1;

    float4 acc[2][8];
    #pragma unroll
    for (int i = 0; i < 2; i++)
        #pragma unroll
        for (int j = 0; j < 8; j++) acc[i][j] = make_float4(0.f, 0.f, 0.f, 0.f);

    float4 ra[4], rb[4];

    #pragma unroll
    for (int i = 0; i < 4; i++) {
        int idx = t + i * 256;
        int row = idx >> 3, kq = (idx & 7) << 2;
        ra[i] = *(const float4*)(resid + (size_t)(r0 + row) * DMODEL + kq);
    }
    if (region < 2) {
        #pragma unroll
        for (int i = 0; i < 4; i++) {
            int idx = t + i * 256;
            int h = idx >> 8, kk = (idx >> 3) & 31, d4 = (idx & 7) << 2;
            rb[i] = *(const float4*)(Wqk + (size_t)(hbase + h) * DMODEL * DQK
                                     + (size_t)kk * DQK + d4);
        }
    } else {
        #pragma unroll
        for (int i = 0; i < 4; i++) {
            int idx = t + i * 256;
            int row = idx >> 3, kq = (idx & 7) << 2;
            rb[i] = *(const float4*)(Bv + (size_t)row * DMODEL + kq);
        }
    }

    for (int kt = 0; kt < 32; kt++) {
        int buf = kt & 1;
        uint32_t* A = As0 + buf * (128 * 36);
        uint32_t* B = Bs0 + buf * (128 * 36);

        #pragma unroll
        for (int i = 0; i < 4; i++) {
            int idx = t + i * 256;
            int row = idx >> 3, kq = (idx & 7) << 2;
            *(uint4*)&A[row * 36 + kq] =
                make_uint4(f2tf(ra[i].x), f2tf(ra[i].y), f2tf(ra[i].z), f2tf(ra[i].w));
        }
        if (region < 2) {
            #pragma unroll
            for (int i = 0; i < 4; i++) {
                int idx = t + i * 256;
                int h = idx >> 8, kk = (idx >> 3) & 31, d4 = (idx & 7) << 2;
                int nn = h * 32 + d4;
                B[(nn    ) * 36 + kk] = f2tf(rb[i].x);
                B[(nn + 1) * 36 + kk] = f2tf(rb[i].y);
                B[(nn + 2) * 36 + kk] = f2tf(rb[i].z);
                B[(nn + 3) * 36 + kk] = f2tf(rb[i].w);
            }
        } else {
            #pragma unroll
            for (int i = 0; i < 4; i++) {
                int idx = t + i * 256;
                int row = idx >> 3, kq = (idx & 7) << 2;
                *(uint4*)&B[row * 36 + kq] =
                    make_uint4(f2tf(rb[i].x), f2tf(rb[i].y), f2tf(rb[i].z), f2tf(rb[i].w));
            }
        }
        __syncthreads();

        if (kt < 31) {
            int k0 = (kt + 1) * 32;
            #pragma unroll
            for (int i = 0; i < 4; i++) {
                int idx = t + i * 256;
                int row = idx >> 3, kq = (idx & 7) << 2;
                ra[i] = *(const float4*)(resid + (size_t)(r0 + row) * DMODEL + k0 + kq);
            }
            if (region < 2) {
                #pragma unroll
                for (int i = 0; i < 4; i++) {
                    int idx = t + i * 256;
                    int h = idx >> 8, kk = (idx >> 3) & 31, d4 = (idx & 7) << 2;
                    rb[i] = *(const float4*)(Wqk + (size_t)(hbase + h) * DMODEL * DQK
                                             + (size_t)(k0 + kk) * DQK + d4);
                }
            } else {
                #pragma unroll
                for (int i = 0; i < 4; i++) {
                    int idx = t + i * 256;
                    int row = idx >> 3, kq = (idx & 7) << 2;
                    rb[i] = *(const float4*)(Bv + (size_t)row * DMODEL + k0 + kq);
                }
            }
        }

        #pragma unroll
        for (int ks = 0; ks < 32; ks += 8) {
            uint32_t af[2][4];
            #pragma unroll
            for (int i = 0; i < 2; i++) {
                int rm = wm * 32 + i * 16;
                af[i][0] = A[(rm + g    ) * 36 + ks + tg];
                af[i][1] = A[(rm + g + 8) * 36 + ks + tg];
                af[i][2] = A[(rm + g    ) * 36 + ks + tg + 4];
                af[i][3] = A[(rm + g + 8) * 36 + ks + tg + 4];
            }
            #pragma unroll
            for (int j = 0; j < 8; j++) {
                int cn = wn * 64 + j * 8 + g;
                uint32_t bf[2] = { B[cn * 36 + ks + tg], B[cn * 36 + ks + tg + 4] };
                mma8(acc[0][j], af[0], bf);
                mma8(acc[1][j], af[1], bf);
            }
        }
    }

    if (region == 2) {
        int nv0 = n0 - 2048;
        #pragma unroll
        for (int i = 0; i < 2; i++) {
            int row0 = r0 + wm * 32 + i * 16 + g;
            #pragma unroll
            for (int j = 0; j < 8; j++) {
                int n = nv0 + wn * 64 + j * 8 + tg * 2;
                float2 bvv = *(const float2*)(bv + n);
                int b1 = row0 >> 10, s1 = row0 & 1023;
                *(float2*)&g_vext[((size_t)b1 * KVLEN + s1) * NOV + n] =
                    make_float2(acc[i][j].x + bvv.x, acc[i][j].y + bvv.y);
                int r2 = row0 + 8;
                int b2 = r2 >> 10, s2 = r2 & 1023;
                *(float2*)&g_vext[((size_t)b2 * KVLEN + s2) * NOV + n] =
                    make_float2(acc[i][j].z + bvv.x, acc[i][j].w + bvv.y);
            }
        }
    } else {
        __syncthreads();
        const float* bias = (region == 0) ? bq : bk;
        #pragma unroll
        for (int i = 0; i < 2; i++) {
            int rr = wm * 32 + i * 16 + g;
            #pragma unroll
            for (int j = 0; j < 8; j++) {
                int c = wn * 64 + j * 8 + tg * 2;
                float b0 = bias[cb + c];
                float b1 = bias[cb + c + 1];
                Cs[rr    ][c    ] = acc[i][j].x + b0;
                Cs[rr    ][c + 1] = acc[i][j].y + b1;
                Cs[rr + 8][c    ] = acc[i][j].z + b0;
                Cs[rr + 8][c + 1] = acc[i][j].w + b1;
            }
        }
        __syncthreads();

        const float invscale = 0.17677669529663687f;
        float sc = (region == 0) ? invscale : 1.f;
        #pragma unroll
        for (int p = 0; p < 2; p++) {
            int idx = t + p * 256;
            int r = idx >> 2, hh = idx & 3;
            int grow = r0 + r;
            int bb = grow >> 10, pos = grow & 1023;
            int h = hbase + hh;
            const float* base = &Cs[r][hh * 32];
            float* dst = (region == 0)
                ? g_q    + (((size_t)bb * NQK + h) * SEQ   + pos) * DQK
                : g_kext + (((size_t)bb * NQK + h) * KVLEN + pos) * DQK;
            #pragma unroll
            for (int c = 0; c < 32; c++) {
                float val  = base[c];
                float flip = (c < 16) ? -base[c + 16] : base[c - 16];
                int jm = c & 15;
                float sn = g_sin[pos * 16 + jm];
                float cs = g_cos[pos * 16 + jm];
                dst[c] = (val * cs + flip * sn) * sc;
            }
        }
    }
}

// ---------------- attention: tf32 mma flash, cp.async double-buffered, shuffle-P ----------------
// grid (8, 32, 2), block 256, 2 CTAs/SM. smem: Kb[2][64*36] + Vb[2][64*72] = 55296 B.
__global__ void __launch_bounds__(256, 2) attn_mma_kernel()
{
    extern __shared__ uint32_t smem[];
    uint32_t* Kb0 = smem;                  // 2 * 2304 words
    uint32_t* Vb0 = smem + 2 * 64 * 36;    // 2 * 4608 words

    int qt = 7 - blockIdx.x;               // big tiles first
    int h = blockIdx.y, b = blockIdx.z;
    int i0 = qt * 128;
    int t = threadIdx.x, w = t >> 5, lane = t & 31;
    int g = lane >> 2, tg = lane & 3;

    const float* kbp = g_kext + ((size_t)b * NQK + h) * KVLEN * DQK;
    const float* vbp = g_vext + (size_t)b * KVLEN * NOV + h * RATIO;

    // Q fragments (pre-scaled; keep rna conversion)
    uint32_t qf[4][4];
    {
        const float* qbase = g_q + (((size_t)b * NQK + h) * SEQ + i0 + w * 16) * DQK;
        #pragma unroll
        for (int kb = 0; kb < 4; kb++) {
            qf[kb][0] = f2tf(qbase[(size_t)g       * DQK + kb * 8 + tg]);
            qf[kb][1] = f2tf(qbase[(size_t)(g + 8) * DQK + kb * 8 + tg]);
            qf[kb][2] = f2tf(qbase[(size_t)g       * DQK + kb * 8 + tg + 4]);
            qf[kb][3] = f2tf(qbase[(size_t)(g + 8) * DQK + kb * 8 + tg + 4]);
        }
    }

    float m_lo = -INFINITY, m_hi = -INFINITY, l_lo = 0.f, l_hi = 0.f;
    float4 z[8];
    #pragma unroll
    for (int j = 0; j < 8; j++) z[j] = make_float4(0.f, 0.f, 0.f, 0.f);

    int row_lo = i0 + w * 16 + g;
    int row_hi = row_lo + 8;

    int jlim = i0 + 128 + VKV;
    if (jlim > KVLEN) jlim = KVLEN;
    int nch = (jlim + 63) >> 6;

    auto issue = [&](int ch) {
        int kv0 = ch << 6;
        uint32_t* K = Kb0 + (ch & 1) * 2304;
        uint32_t* V = Vb0 + (ch & 1) * 4608;
        #pragma unroll
        for (int i = 0; i < 2; i++) {
            int idx = t + i * 256;
            int row = idx >> 3, c4 = (idx & 7) << 2;
            int gj = kv0 + row;
            int cg2 = gj < KVLEN ? gj : KVLEN - 1;
            uint32_t dst = (uint32_t)__cvta_generic_to_shared(&K[row * 36 + c4]);
            cp_async16(dst, kbp + (size_t)cg2 * DQK + c4, gj < KVLEN ? 16 : 0);
        }
        #pragma unroll
        for (int i = 0; i < 4; i++) {
            int idx = t + i * 256;
            int row = idx >> 4, c4 = (idx & 15) << 2;
            int gj = kv0 + row;
            int cg2 = gj < KVLEN ? gj : KVLEN - 1;
            uint32_t dst = (uint32_t)__cvta_generic_to_shared(&V[row * 72 + c4]);
            cp_async16(dst, vbp + (size_t)cg2 * NOV + c4, gj < KVLEN ? 16 : 0);
        }
        asm volatile("cp.async.commit_group;" ::: "memory");
    };

    issue(0);

    for (int ch = 0; ch < nch; ch++) {
        int kv0 = ch << 6;
        if (ch + 1 < nch) {
            issue(ch + 1);
            asm volatile("cp.async.wait_group 1;" ::: "memory");
        } else {
            asm volatile("cp.async.wait_group 0;" ::: "memory");
        }
        __syncthreads();

        uint32_t* K = Kb0 + (ch & 1) * 2304;
        uint32_t* V = Vb0 + (ch & 1) * 4608;

        // S = Q K^T  [16 x 64] per warp (raw f32 bits; mma truncates to tf32)
        float4 s[8];
        #pragma unroll
        for (int j = 0; j < 8; j++) s[j] = make_float4(0.f, 0.f, 0.f, 0.f);
        #pragma unroll
        for (int ks = 0; ks < 4; ks++) {
            #pragma unroll
            for (int j = 0; j < 8; j++) {
                int cn = j * 8 + g;
                uint32_t bf[2] = { K[cn * 36 + ks * 8 + tg], K[cn * 36 + ks * 8 + tg + 4] };
                mma8(s[j], qf[ks], bf);
            }
        }

        // mask
        #pragma unroll
        for (int j = 0; j < 8; j++) {
            int c0 = kv0 + j * 8 + 2 * tg;
            int c1 = c0 + 1;
            s[j].x = (c0 <= row_lo + VKV && c0 < KVLEN) ? s[j].x : -INFINITY;
            s[j].y = (c1 <= row_lo + VKV && c1 < KVLEN) ? s[j].y : -INFINITY;
            s[j].z = (c0 <= row_hi + VKV && c0 < KVLEN) ? s[j].z : -INFINITY;
            s[j].w = (c1 <= row_hi + VKV && c1 < KVLEN) ? s[j].w : -INFINITY;
        }

        // online softmax
        float mx_lo = -INFINITY, mx_hi = -INFINITY;
        #pragma unroll
        for (int j = 0; j < 8; j++) {
            mx_lo = fmaxf(mx_lo, fmaxf(s[j].x, s[j].y));
            mx_hi = fmaxf(mx_hi, fmaxf(s[j].z, s[j].w));
        }
        mx_lo = fmaxf(mx_lo, __shfl_xor_sync(FULLM, mx_lo, 1));
        mx_lo = fmaxf(mx_lo, __shfl_xor_sync(FULLM, mx_lo, 2));
        mx_hi = fmaxf(mx_hi, __shfl_xor_sync(FULLM, mx_hi, 1));
        mx_hi = fmaxf(mx_hi, __shfl_xor_sync(FULLM, mx_hi, 2));
        float mn_lo = fmaxf(m_lo, mx_lo);
        float mn_hi = fmaxf(m_hi, mx_hi);
        float corr_lo = __expf(m_lo - mn_lo);
        float corr_hi = __expf(m_hi - mn_hi);

        float ps_lo = 0.f, ps_hi = 0.f;
        #pragma unroll
        for (int j = 0; j < 8; j++) {
            s[j].x = __expf(s[j].x - mn_lo);
            s[j].y = __expf(s[j].y - mn_lo);
            s[j].z = __expf(s[j].z - mn_hi);
            s[j].w = __expf(s[j].w - mn_hi);
            ps_lo += s[j].x + s[j].y;
            ps_hi += s[j].z + s[j].w;
        }
        ps_lo += __shfl_xor_sync(FULLM, ps_lo, 1);
        ps_lo += __shfl_xor_sync(FULLM, ps_lo, 2);
        ps_hi += __shfl_xor_sync(FULLM, ps_hi, 1);
        ps_hi += __shfl_xor_sync(FULLM, ps_hi, 2);
        l_lo = l_lo * corr_lo + ps_lo;
        l_hi = l_hi * corr_hi + ps_hi;
        m_lo = mn_lo; m_hi = mn_hi;
        #pragma unroll
        for (int j = 0; j < 8; j++) {
            z[j].x *= corr_lo; z[j].y *= corr_lo;
            z[j].z *= corr_hi; z[j].w *= corr_hi;
        }

        // Z += P V with P fragments built by shuffle (C-frag layout -> A-frag layout)
        int srcA = (lane & ~3) | (tg >> 1);
        int srcB = srcA | 2;
        bool odd = (tg & 1) != 0;
        #pragma unroll
        for (int ks = 0; ks < 8; ks++) {
            float xl  = __shfl_sync(FULLM, s[ks].x, srcA);
            float yl  = __shfl_sync(FULLM, s[ks].y, srcA);
            float xh  = __shfl_sync(FULLM, s[ks].z, srcA);
            float yh  = __shfl_sync(FULLM, s[ks].w, srcA);
            float xl2 = __shfl_sync(FULLM, s[ks].x, srcB);
            float yl2 = __shfl_sync(FULLM, s[ks].y, srcB);
            float xh2 = __shfl_sync(FULLM, s[ks].z, srcB);
            float yh2 = __shfl_sync(FULLM, s[ks].w, srcB);
            uint32_t af[4];
            af[0] = __float_as_uint(odd ? yl  : xl );
            af[1] = __float_as_uint(odd ? yh  : xh );
            af[2] = __float_as_uint(odd ? yl2 : xl2);
            af[3] = __float_as_uint(odd ? yh2 : xh2);
            #pragma unroll
            for (int j = 0; j < 8; j++) {
                int cn = j * 8 + g;
                uint32_t bf[2] = { V[(ks * 8 + tg) * 72 + cn], V[(ks * 8 + tg + 4) * 72 + cn] };
                mma8(z[j], af, bf);
            }
        }
        __syncthreads();   // all reads of this buffer done before it is refilled
    }

    float li_lo = 1.f / l_lo;
    float li_hi = 1.f / l_hi;
    float* zlo = g_z + ((size_t)b * SEQ + row_lo) * NOV + h * RATIO;
    float* zhi = g_z + ((size_t)b * SEQ + row_hi) * NOV + h * RATIO;
    #pragma unroll
    for (int j = 0; j < 8; j++) {
        int col = j * 8 + 2 * tg;
        *(float2*)&zlo[col] = make_float2(z[j].x * li_lo, z[j].y * li_lo);
        *(float2*)&zhi[col] = make_float2(z[j].z * li_hi, z[j].w * li_hi);
    }
}

// ---------------- output GEMM (tf32 mma, NN, pipelined): BM=128, BN=128 ----------------
__global__ void __launch_bounds__(256) out_gemm_kernel(
    const float* __restrict__ Wo, float* __restrict__ out)
{
    extern __shared__ uint32_t dsm[];
    uint32_t* As0 = dsm;                  // [2][128][36]
    uint32_t* Bs0 = dsm + 2 * 128 * 36;   // [2][32][132]

    int n0 = blockIdx.x * 128, r0 = blockIdx.y * 128;
    int t = threadIdx.x;
    int w = t >> 5, lane = t & 31;
    int g = lane >> 2, tg = lane & 3;
    int wm = w >> 1, wn = w & 1;

    float4 acc[2][8];
    #pragma unroll
    for (int i = 0; i < 2; i++)
        #pragma unroll
        for (int j = 0; j < 8; j++) acc[i][j] = make_float4(0.f, 0.f, 0.f, 0.f);

    float4 ra[4], rb[4];
    #pragma unroll
    for (int i = 0; i < 4; i++) {
        int idx = t + i * 256;
        int row = idx >> 3, kq = (idx & 7) << 2;
        ra[i] = *(const float4*)(g_z + (size_t)(r0 + row) * NOV + kq);
    }
    #pragma unroll
    for (int i = 0; i < 4; i++) {
        int idx = t + i * 256;
        int kk = idx >> 5, nq = (idx & 31) << 2;
        rb[i] = *(const float4*)(Wo + (size_t)kk * DMODEL + n0 + nq);
    }

    for (int kt = 0; kt < 64; kt++) {
        int buf = kt & 1;
        uint32_t* A = As0 + buf * (128 * 36);
        uint32_t* B = Bs0 + buf * (32 * 132);

        #pragma unroll
        for (int i = 0; i < 4; i++) {
            int idx = t + i * 256;
            int row = idx >> 3, kq = (idx & 7) << 2;
            *(uint4*)&A[row * 36 + kq] =
                make_uint4(f2tf(ra[i].x), f2tf(ra[i].y), f2tf(ra[i].z), f2tf(ra[i].w));
        }
        #pragma unroll
        for (int i = 0; i < 4; i++) {
            int idx = t + i * 256;
            int kk = idx >> 5, nq = (idx & 31) << 2;
            *(uint4*)&B[kk * 132 + nq] =
                make_uint4(f2tf(rb[i].x), f2tf(rb[i].y), f2tf(rb[i].z), f2tf(rb[i].w));
        }
        __syncthreads();

        if (kt < 63) {
            int k0 = (kt + 1) * 32;
            #pragma unroll
            for (int i = 0; i < 4; i++) {
                int idx = t + i * 256;
                int row = idx >> 3, kq = (idx & 7) << 2;
                ra[i] = *(const float4*)(g_z + (size_t)(r0 + row) * NOV + k0 + kq);
            }
            #pragma unroll
            for (int i = 0; i < 4; i++) {
                int idx = t + i * 256;
                int kk = idx >> 5, nq = (idx & 31) << 2;
                rb[i] = *(const float4*)(Wo + (size_t)(k0 + kk) * DMODEL + n0 + nq);
            }
        }

        #pragma unroll
        for (int ks = 0; ks < 32; ks += 8) {
            uint32_t af[2][4];
            #pragma unroll
            for (int i = 0; i < 2; i++) {
                int rm = wm * 32 + i * 16;
                af[i][0] = A[(rm + g    ) * 36 + ks + tg];
                af[i][1] = A[(rm + g + 8) * 36 + ks + tg];
                af[i][2] = A[(rm + g    ) * 36 + ks + tg + 4];
                af[i][3] = A[(rm + g + 8) * 36 + ks + tg + 4];
            }
            #pragma unroll
            for (int j = 0; j < 8; j++) {
                int cn = wn * 64 + j * 8 + g;
                uint32_t bf[2] = { B[(ks + tg) * 132 + cn], B[(ks + tg + 4) * 132 + cn] };
                mma8(acc[0][j], af[0], bf);
                mma8(acc[1][j], af[1], bf);
            }
        }
    }

    #pragma unroll
    for (int i = 0; i < 2; i++) {
        int row0 = r0 + wm * 32 + i * 16 + g;
        #pragma unroll
        for (int j = 0; j < 8; j++) {
            int n = n0 + wn * 64 + j * 8 + tg * 2;
            *(float2*)&out[(size_t)row0 * DMODEL + n] = make_float2(acc[i][j].x, acc[i][j].y);
            *(float2*)&out[(size_t)(row0 + 8) * DMODEL + n] = make_float2(acc[i][j].z, acc[i][j].w);
        }
    }
}

// ---------------- launch ----------------
extern "C" void kernel_launch(void* const* d_in, const int* in_sizes, int n_in,
                              void* d_out, int out_size)
{
    const float* resid = (const float*)d_in[0];
    const float* Wq    = (const float*)d_in[1];
    const float* Wk    = (const float*)d_in[2];
    const float* Wv    = (const float*)d_in[3];
    const float* Wo    = (const float*)d_in[4];
    const float* bq    = (const float*)d_in[5];
    const float* bk    = (const float*)d_in[6];
    const float* bv    = (const float*)d_in[7];
    const float* vk    = (const float*)d_in[8];
    const float* vv    = (const float*)d_in[9];
    float* out = (float*)d_out;

    const int ATTN_SMEM = (2 * 64 * 36 + 2 * 64 * 72) * 4;     // 55296
    const int QKV_SMEM  = (2 * 128 * 36 + 2 * 128 * 36) * 4;   // 73728
    const int OUT_SMEM  = (2 * 128 * 36 + 2 * 32 * 132) * 4;   // 70656
    static int smem_set = 0;
    if (!smem_set) {
        cudaFuncSetAttribute(attn_mma_kernel,
                             cudaFuncAttributeMaxDynamicSharedMemorySize, ATTN_SMEM);
        cudaFuncSetAttribute(qkv_gemm_kernel,
                             cudaFuncAttributeMaxDynamicSharedMemorySize, QKV_SMEM);
        cudaFuncSetAttribute(out_gemm_kernel,
                             cudaFuncAttributeMaxDynamicSharedMemorySize, OUT_SMEM);
        smem_set = 1;
    }

    rot_init_kernel<<<64, 256>>>();
    copy_virtual_kernel<<<256, 256>>>(vk, vv);
    qkv_gemm_kernel<<<dim3(32, 16), 256, QKV_SMEM>>>(resid, Wq, Wk, Wv, bq, bk, bv);
    attn_mma_kernel<<<dim3(8, 32, 2), 256, ATTN_SMEM>>>();
    out_gemm_kernel<<<dim3(8, 16), 256, OUT_SMEM>>>(Wo, out);
}